// round 1
// baseline (speedup 1.0000x reference)
#include <cuda_runtime.h>
#include <math.h>

// Problem constants (fixed shapes from reference)
#define BATCH   4
#define SEQ     8192
#define DIM     768
#define CHUNK   64
#define M_ROWS  (BATCH * SEQ)       // 32768 tokens
#define DFF     (4 * DIM)           // 3072
#define NCHUNKS (M_ROWS / CHUNK)    // 512

// ---------------- scratch (static device globals; no runtime allocation) ----
__device__ float g_h  [(size_t)M_ROWS * DIM];   // h / h2        (100 MB)
__device__ float g_g  [(size_t)M_ROWS * DIM];   // gate          (100 MB)
__device__ float g_v  [(size_t)M_ROWS * DIM];   // value -> mem  (100 MB)
__device__ float g_ffn[(size_t)M_ROWS * DFF];   // ffn hidden    (403 MB)

// ---------------- block-wide sum over 256 threads ---------------------------
__device__ __forceinline__ float block_sum_256(float v) {
    __shared__ float sh[8];
    int lane = threadIdx.x & 31;
    int wrp  = threadIdx.x >> 5;
    #pragma unroll
    for (int o = 16; o > 0; o >>= 1) v += __shfl_xor_sync(0xffffffffu, v, o);
    if (lane == 0) sh[wrp] = v;
    __syncthreads();
    if (wrp == 0) {
        float t = (lane < 8) ? sh[lane] : 0.0f;
        #pragma unroll
        for (int o = 4; o > 0; o >>= 1) t += __shfl_xor_sync(0xffffffffu, t, o);
        if (lane == 0) sh[0] = t;
    }
    __syncthreads();
    float r = sh[0];
    __syncthreads();   // protect sh for a subsequent call
    return r;
}

// ---------------- LayerNorm (optionally x += mem first) ---------------------
// 256 threads per row of 768; each thread owns 3 columns.
template <bool ADD_MEM>
__global__ void ln_kernel(const float* __restrict__ x,
                          const float* __restrict__ mem,
                          const float* __restrict__ w,
                          const float* __restrict__ b,
                          float* __restrict__ xout,   // only used if ADD_MEM
                          float* __restrict__ hout) {
    const size_t row = blockIdx.x;
    const size_t base = row * DIM;
    const int tid = threadIdx.x;

    float vals[3];
    #pragma unroll
    for (int i = 0; i < 3; i++) {
        int c = tid + i * 256;
        float xv = x[base + c];
        if (ADD_MEM) {
            xv += mem[base + c];
            xout[base + c] = xv;
        }
        vals[i] = xv;
    }
    float s = vals[0] + vals[1] + vals[2];
    float mu = block_sum_256(s) * (1.0f / DIM);

    float sq = 0.0f;
    #pragma unroll
    for (int i = 0; i < 3; i++) {
        float d = vals[i] - mu;
        sq += d * d;
    }
    float var = block_sum_256(sq) * (1.0f / DIM);
    float inv = rsqrtf(var + 1e-5f);

    #pragma unroll
    for (int i = 0; i < 3; i++) {
        int c = tid + i * 256;
        hout[base + c] = (vals[i] - mu) * inv * w[c] + b[c];
    }
}

// ---------------- tiled SGEMM: C = act(A[M,K] @ W[K,N] + bias) (+= C) -------
#define BM 64
#define BN 64
#define BK 16

#define ACT_NONE 0
#define ACT_SIG  1
#define ACT_GELU 2

template <int ACT, bool ADD_OUT>
__global__ __launch_bounds__(256)
void gemm_kernel(const float* __restrict__ A,
                 const float* __restrict__ W,
                 const float* __restrict__ bias,
                 float* __restrict__ C,
                 int N, int K) {
    __shared__ float As[BK][BM + 4];
    __shared__ float Bs[BK][BN];

    const int tid = threadIdx.x;
    const int bm = blockIdx.y * BM;
    const int bn = blockIdx.x * BN;

    const int arow = tid >> 2;          // 0..63
    const int acol = (tid & 3) * 4;     // 0,4,8,12
    const int brow = tid >> 4;          // 0..15
    const int bcol = (tid & 15) * 4;    // 0..60

    const int ty = tid >> 4;            // 0..15 -> 4 output rows
    const int tx = tid & 15;            // 0..15 -> 4 output cols

    float acc[4][4] = {};

    for (int k0 = 0; k0 < K; k0 += BK) {
        float4 a4 = *reinterpret_cast<const float4*>(
            A + (size_t)(bm + arow) * K + k0 + acol);
        As[acol + 0][arow] = a4.x;
        As[acol + 1][arow] = a4.y;
        As[acol + 2][arow] = a4.z;
        As[acol + 3][arow] = a4.w;

        float4 b4 = *reinterpret_cast<const float4*>(
            W + (size_t)(k0 + brow) * N + bn + bcol);
        *reinterpret_cast<float4*>(&Bs[brow][bcol]) = b4;

        __syncthreads();

        #pragma unroll
        for (int k = 0; k < BK; k++) {
            float a[4], bv[4];
            #pragma unroll
            for (int i = 0; i < 4; i++) a[i]  = As[k][ty * 4 + i];
            #pragma unroll
            for (int j = 0; j < 4; j++) bv[j] = Bs[k][tx * 4 + j];
            #pragma unroll
            for (int i = 0; i < 4; i++)
                #pragma unroll
                for (int j = 0; j < 4; j++)
                    acc[i][j] = fmaf(a[i], bv[j], acc[i][j]);
        }
        __syncthreads();
    }

    #pragma unroll
    for (int i = 0; i < 4; i++) {
        const size_t r = bm + ty * 4 + i;
        #pragma unroll
        for (int j = 0; j < 4; j++) {
            const int c = bn + tx * 4 + j;
            float val = acc[i][j] + bias[c];
            if (ACT == ACT_SIG)  val = 1.0f / (1.0f + expf(-val));
            if (ACT == ACT_GELU) val = 0.5f * val * (1.0f + erff(val * 0.70710678118654752f));
            const size_t idx = r * N + c;
            if (ADD_OUT) val += C[idx];
            C[idx] = val;
        }
    }
}

// ---------------- chunked normalized cumulative sum -------------------------
// One thread per (chunk, column). mem overwrites V in place.
__global__ void scan_kernel(const float* __restrict__ G, float* __restrict__ V) {
    const int col   = blockIdx.x * 256 + threadIdx.x;   // 0..767
    const int chunk = blockIdx.y;                       // 0..511
    size_t idx = (size_t)chunk * CHUNK * DIM + col;
    float sg = 0.0f, sgv = 0.0f;
    #pragma unroll 4
    for (int t = 0; t < CHUNK; t++) {
        float g = G[idx];
        float v = V[idx];
        sg  += g;
        sgv += g * v;
        V[idx] = sgv / (sg + 1e-6f);
        idx += DIM;
    }
}

// ---------------- launcher ---------------------------------------------------
extern "C" void kernel_launch(void* const* d_in, const int* in_sizes, int n_in,
                              void* d_out, int out_size) {
    const float* x       = (const float*)d_in[0];
    const float* n1w     = (const float*)d_in[1];
    const float* n1b     = (const float*)d_in[2];
    const float* n2w     = (const float*)d_in[3];
    const float* n2b     = (const float*)d_in[4];
    const float* gate_W  = (const float*)d_in[5];
    const float* gate_b  = (const float*)d_in[6];
    const float* value_W = (const float*)d_in[7];
    const float* value_b = (const float*)d_in[8];
    const float* ffn_W1  = (const float*)d_in[9];
    const float* ffn_b1  = (const float*)d_in[10];
    const float* ffn_W2  = (const float*)d_in[11];
    const float* ffn_b2  = (const float*)d_in[12];
    float* out = (float*)d_out;

    float *h, *g, *v, *ffn;
    cudaGetSymbolAddress((void**)&h,   g_h);
    cudaGetSymbolAddress((void**)&g,   g_g);
    cudaGetSymbolAddress((void**)&v,   g_v);
    cudaGetSymbolAddress((void**)&ffn, g_ffn);

    // 1. h = LN1(x)
    ln_kernel<false><<<M_ROWS, 256>>>(x, nullptr, n1w, n1b, nullptr, h);

    // 2. g = sigmoid(h @ gate_W + gate_b)
    {
        dim3 grid(DIM / BN, M_ROWS / BM);
        gemm_kernel<ACT_SIG, false><<<grid, 256>>>(h, gate_W, gate_b, g, DIM, DIM);
    }
    // 3. v = h @ value_W + value_b
    {
        dim3 grid(DIM / BN, M_ROWS / BM);
        gemm_kernel<ACT_NONE, false><<<grid, 256>>>(h, value_W, value_b, v, DIM, DIM);
    }
    // 4. v <- mem (chunked normalized cumsum, in place)
    {
        dim3 grid(DIM / 256, NCHUNKS);
        scan_kernel<<<grid, 256>>>(g, v);
    }
    // 5. out = x + mem ; h = LN2(out)
    ln_kernel<true><<<M_ROWS, 256>>>(x, v, n2w, n2b, out, h);

    // 6. ffn_hidden = gelu(h @ W1 + b1)
    {
        dim3 grid(DFF / BN, M_ROWS / BM);
        gemm_kernel<ACT_GELU, false><<<grid, 256>>>(h, ffn_W1, ffn_b1, ffn, DFF, DIM);
    }
    // 7. out += ffn_hidden @ W2 + b2
    {
        dim3 grid(DIM / BN, M_ROWS / BM);
        gemm_kernel<ACT_NONE, true><<<grid, 256>>>(ffn, ffn_W2, ffn_b2, out, DIM, DFF);
    }
}

// round 2
// speedup vs baseline: 2.6374x; 2.6374x over previous
#include <cuda_runtime.h>
#include <mma.h>
#include <math.h>

using namespace nvcuda;

// Problem constants (fixed shapes from reference)
#define BATCH   4
#define SEQ     8192
#define DIM     768
#define CHUNK   64
#define M_ROWS  (BATCH * SEQ)       // 32768 tokens
#define DFF     (4 * DIM)           // 3072
#define NCHUNKS (M_ROWS / CHUNK)    // 512

// ---------------- scratch (static device globals; no runtime allocation) ----
__device__ float g_h  [(size_t)M_ROWS * DIM];   // h / h2
__device__ float g_g  [(size_t)M_ROWS * DIM];   // gate
__device__ float g_v  [(size_t)M_ROWS * DIM];   // value -> mem
__device__ float g_ffn[(size_t)M_ROWS * DFF];   // ffn hidden

// ---------------- block-wide sum over 256 threads ---------------------------
__device__ __forceinline__ float block_sum_256(float v) {
    __shared__ float sh[8];
    int lane = threadIdx.x & 31;
    int wrp  = threadIdx.x >> 5;
    #pragma unroll
    for (int o = 16; o > 0; o >>= 1) v += __shfl_xor_sync(0xffffffffu, v, o);
    if (lane == 0) sh[wrp] = v;
    __syncthreads();
    if (wrp == 0) {
        float t = (lane < 8) ? sh[lane] : 0.0f;
        #pragma unroll
        for (int o = 4; o > 0; o >>= 1) t += __shfl_xor_sync(0xffffffffu, t, o);
        if (lane == 0) sh[0] = t;
    }
    __syncthreads();
    float r = sh[0];
    __syncthreads();
    return r;
}

// ---------------- LayerNorm (optionally x += mem first) ---------------------
template <bool ADD_MEM>
__global__ void ln_kernel(const float* __restrict__ x,
                          const float* __restrict__ mem,
                          const float* __restrict__ w,
                          const float* __restrict__ b,
                          float* __restrict__ xout,
                          float* __restrict__ hout) {
    const size_t row = blockIdx.x;
    const size_t base = row * DIM;
    const int tid = threadIdx.x;

    float vals[3];
    #pragma unroll
    for (int i = 0; i < 3; i++) {
        int c = tid + i * 256;
        float xv = x[base + c];
        if (ADD_MEM) {
            xv += mem[base + c];
            xout[base + c] = xv;
        }
        vals[i] = xv;
    }
    float s = vals[0] + vals[1] + vals[2];
    float mu = block_sum_256(s) * (1.0f / DIM);

    float sq = 0.0f;
    #pragma unroll
    for (int i = 0; i < 3; i++) {
        float d = vals[i] - mu;
        sq += d * d;
    }
    float var = block_sum_256(sq) * (1.0f / DIM);
    float inv = rsqrtf(var + 1e-5f);

    #pragma unroll
    for (int i = 0; i < 3; i++) {
        int c = tid + i * 256;
        hout[base + c] = (vals[i] - mu) * inv * w[c] + b[c];
    }
}

// ---------------- tf32 wmma GEMM: C = act(A[M,K] @ W[K,N] + bias) (+= C) ----
// Block tile 128x64, 8 warps (4x2) at 32x32 warp tiles, K-tile 32.
// Register-prefetch software pipeline over global loads.
#define BM 128
#define BN 64
#define KT 32
#define LDA 36              // A smem leading dim (row-major [BM][LDA])
#define LDB 68              // B smem leading dim (row-major [KT][LDB])
#define LDC 68              // C staging leading dim

#define ACT_NONE 0
#define ACT_SIG  1
#define ACT_GELU 2

template <int ACT, bool ADD_OUT>
__global__ __launch_bounds__(256)
void gemm_tf32_kernel(const float* __restrict__ A,
                      const float* __restrict__ W,
                      const float* __restrict__ bias,
                      float* __restrict__ C,
                      int N, int K) {
    // Union: A+B tiles during mainloop (128*36 + 32*68 = 6784 floats),
    // C staging in epilogue (128*68 = 8704 floats).
    __shared__ float smem[BM * LDA + KT * LDB > BM * LDC ? BM * LDA + KT * LDB
                                                         : BM * LDC];
    float (*As)[LDA] = (float(*)[LDA])smem;
    float (*Bs)[LDB] = (float(*)[LDB])(smem + BM * LDA);

    const int tid = threadIdx.x;
    const int bm = blockIdx.y * BM;
    const int bn = blockIdx.x * BN;

    // A tile load map: 128x32 floats = 1024 float4; 4 per thread.
    // f = tid + i*256 -> row = f/8, kcol = (f%8)*4
    // B tile load map: 32x64 floats = 512 float4; 2 per thread.
    // f = tid + i*256 -> row = f/16, col = (f%16)*4

    const int wid = tid >> 5;
    const int wm = wid & 3;       // 0..3 -> 4 warp rows
    const int wn = wid >> 2;      // 0..1 -> 2 warp cols

    wmma::fragment<wmma::accumulator, 16, 16, 8, float> acc[2][2];
    #pragma unroll
    for (int i = 0; i < 2; i++)
        #pragma unroll
        for (int j = 0; j < 2; j++)
            wmma::fill_fragment(acc[i][j], 0.0f);

    // Prefetch first K-tile into registers
    float4 pa[4], pb[2];
    #pragma unroll
    for (int i = 0; i < 4; i++) {
        int f = tid + i * 256;
        pa[i] = *reinterpret_cast<const float4*>(
            A + (size_t)(bm + (f >> 3)) * K + ((f & 7) << 2));
    }
    #pragma unroll
    for (int i = 0; i < 2; i++) {
        int f = tid + i * 256;
        pb[i] = *reinterpret_cast<const float4*>(
            W + (size_t)(f >> 4) * N + bn + ((f & 15) << 2));
    }

    for (int k0 = 0; k0 < K; k0 += KT) {
        // Commit prefetched tile to smem (convert to tf32)
        #pragma unroll
        for (int i = 0; i < 4; i++) {
            int f = tid + i * 256;
            int r = f >> 3, c = (f & 7) << 2;
            As[r][c + 0] = wmma::__float_to_tf32(pa[i].x);
            As[r][c + 1] = wmma::__float_to_tf32(pa[i].y);
            As[r][c + 2] = wmma::__float_to_tf32(pa[i].z);
            As[r][c + 3] = wmma::__float_to_tf32(pa[i].w);
        }
        #pragma unroll
        for (int i = 0; i < 2; i++) {
            int f = tid + i * 256;
            int r = f >> 4, c = (f & 15) << 2;
            Bs[r][c + 0] = wmma::__float_to_tf32(pb[i].x);
            Bs[r][c + 1] = wmma::__float_to_tf32(pb[i].y);
            Bs[r][c + 2] = wmma::__float_to_tf32(pb[i].z);
            Bs[r][c + 3] = wmma::__float_to_tf32(pb[i].w);
        }
        __syncthreads();

        // Prefetch next K-tile
        int kn = k0 + KT;
        if (kn < K) {
            #pragma unroll
            for (int i = 0; i < 4; i++) {
                int f = tid + i * 256;
                pa[i] = *reinterpret_cast<const float4*>(
                    A + (size_t)(bm + (f >> 3)) * K + kn + ((f & 7) << 2));
            }
            #pragma unroll
            for (int i = 0; i < 2; i++) {
                int f = tid + i * 256;
                pb[i] = *reinterpret_cast<const float4*>(
                    W + (size_t)(kn + (f >> 4)) * N + bn + ((f & 15) << 2));
            }
        }

        // Compute on the committed tile
        #pragma unroll
        for (int kk = 0; kk < KT; kk += 8) {
            wmma::fragment<wmma::matrix_a, 16, 16, 8, wmma::precision::tf32,
                           wmma::row_major> af[2];
            wmma::fragment<wmma::matrix_b, 16, 16, 8, wmma::precision::tf32,
                           wmma::row_major> bf[2];
            #pragma unroll
            for (int i = 0; i < 2; i++)
                wmma::load_matrix_sync(af[i], &As[wm * 32 + i * 16][kk], LDA);
            #pragma unroll
            for (int j = 0; j < 2; j++)
                wmma::load_matrix_sync(bf[j], &Bs[kk][wn * 32 + j * 16], LDB);
            #pragma unroll
            for (int i = 0; i < 2; i++)
                #pragma unroll
                for (int j = 0; j < 2; j++)
                    wmma::mma_sync(acc[i][j], af[i], bf[j], acc[i][j]);
        }
        __syncthreads();
    }

    // Epilogue: stage to smem (aliases As/Bs), then fused bias + activation
    float (*Cs)[LDC] = (float(*)[LDC])smem;
    #pragma unroll
    for (int i = 0; i < 2; i++)
        #pragma unroll
        for (int j = 0; j < 2; j++)
            wmma::store_matrix_sync(&Cs[wm * 32 + i * 16][wn * 32 + j * 16],
                                    acc[i][j], LDC, wmma::mem_row_major);
    __syncthreads();

    #pragma unroll
    for (int e = 0; e < (BM * BN) / 256; e++) {
        int idx = tid + e * 256;
        int r = idx >> 6;            // /64
        int c = idx & 63;
        float val = Cs[r][c] + bias[bn + c];
        if (ACT == ACT_SIG)  val = 1.0f / (1.0f + expf(-val));
        if (ACT == ACT_GELU) val = 0.5f * val * (1.0f + erff(val * 0.70710678118654752f));
        const size_t gidx = (size_t)(bm + r) * N + bn + c;
        if (ADD_OUT) val += C[gidx];
        C[gidx] = val;
    }
}

// ---------------- chunked normalized cumulative sum -------------------------
__global__ void scan_kernel(const float* __restrict__ G, float* __restrict__ V) {
    const int col   = blockIdx.x * 256 + threadIdx.x;
    const int chunk = blockIdx.y;
    size_t idx = (size_t)chunk * CHUNK * DIM + col;
    float sg = 0.0f, sgv = 0.0f;
    #pragma unroll 4
    for (int t = 0; t < CHUNK; t++) {
        float g = G[idx];
        float v = V[idx];
        sg  += g;
        sgv += g * v;
        V[idx] = sgv / (sg + 1e-6f);
        idx += DIM;
    }
}

// ---------------- launcher ---------------------------------------------------
extern "C" void kernel_launch(void* const* d_in, const int* in_sizes, int n_in,
                              void* d_out, int out_size) {
    const float* x       = (const float*)d_in[0];
    const float* n1w     = (const float*)d_in[1];
    const float* n1b     = (const float*)d_in[2];
    const float* n2w     = (const float*)d_in[3];
    const float* n2b     = (const float*)d_in[4];
    const float* gate_W  = (const float*)d_in[5];
    const float* gate_b  = (const float*)d_in[6];
    const float* value_W = (const float*)d_in[7];
    const float* value_b = (const float*)d_in[8];
    const float* ffn_W1  = (const float*)d_in[9];
    const float* ffn_b1  = (const float*)d_in[10];
    const float* ffn_W2  = (const float*)d_in[11];
    const float* ffn_b2  = (const float*)d_in[12];
    float* out = (float*)d_out;

    float *h, *g, *v, *ffn;
    cudaGetSymbolAddress((void**)&h,   g_h);
    cudaGetSymbolAddress((void**)&g,   g_g);
    cudaGetSymbolAddress((void**)&v,   g_v);
    cudaGetSymbolAddress((void**)&ffn, g_ffn);

    // 1. h = LN1(x)
    ln_kernel<false><<<M_ROWS, 256>>>(x, nullptr, n1w, n1b, nullptr, h);

    // 2. g = sigmoid(h @ gate_W + gate_b)
    {
        dim3 grid(DIM / BN, M_ROWS / BM);
        gemm_tf32_kernel<ACT_SIG, false><<<grid, 256>>>(h, gate_W, gate_b, g, DIM, DIM);
    }
    // 3. v = h @ value_W + value_b
    {
        dim3 grid(DIM / BN, M_ROWS / BM);
        gemm_tf32_kernel<ACT_NONE, false><<<grid, 256>>>(h, value_W, value_b, v, DIM, DIM);
    }
    // 4. v <- mem (chunked normalized cumsum, in place)
    {
        dim3 grid(DIM / 256, NCHUNKS);
        scan_kernel<<<grid, 256>>>(g, v);
    }
    // 5. out = x + mem ; h = LN2(out)
    ln_kernel<true><<<M_ROWS, 256>>>(x, v, n2w, n2b, out, h);

    // 6. ffn_hidden = gelu(h @ W1 + b1)
    {
        dim3 grid(DFF / BN, M_ROWS / BM);
        gemm_tf32_kernel<ACT_GELU, false><<<grid, 256>>>(h, ffn_W1, ffn_b1, ffn, DFF, DIM);
    }
    // 7. out += ffn_hidden @ W2 + b2
    {
        dim3 grid(DIM / BN, M_ROWS / BM);
        gemm_tf32_kernel<ACT_NONE, true><<<grid, 256>>>(ffn, ffn_W2, ffn_b2, out, DIM, DFF);
    }
}

// round 4
// speedup vs baseline: 7.6531x; 2.9017x over previous
#include <cuda_runtime.h>
#include <cuda_fp16.h>
#include <mma.h>
#include <math.h>
#include <stdint.h>

using namespace nvcuda;

// Problem constants
#define BATCH   4
#define SEQ     8192
#define DIM     768
#define CHUNK   64
#define M_ROWS  (BATCH * SEQ)       // 32768
#define DFF     (4 * DIM)           // 3072
#define NCHUNKS (M_ROWS / CHUNK)    // 512

// ---------------- scratch (static device globals) ----------------------------
__device__ __half g_h   [(size_t)M_ROWS * DIM];   // LN output (half)
__device__ float  g_g   [(size_t)M_ROWS * DIM];   // gate (f32, scan input)
__device__ float  g_v   [(size_t)M_ROWS * DIM];   // value -> mem (f32)
__device__ __half g_ffn [(size_t)M_ROWS * DFF];   // ffn hidden (half)
__device__ __half g_wg  [(size_t)DIM * DIM];      // gate_W  half [K,N]
__device__ __half g_wv  [(size_t)DIM * DIM];      // value_W half
__device__ __half g_w1  [(size_t)DIM * DFF];      // ffn_W1  half
__device__ __half g_w2  [(size_t)DFF * DIM];      // ffn_W2  half

// ---------------- cp.async helpers -------------------------------------------
__device__ __forceinline__ uint32_t smem_u32(const void* p) {
    uint32_t a;
    asm("{ .reg .u64 t; cvta.to.shared.u64 t, %1; cvt.u32.u64 %0, t; }"
        : "=r"(a) : "l"(p));
    return a;
}
#define CP_ASYNC16(dst, src) \
    asm volatile("cp.async.cg.shared.global [%0], [%1], 16;" :: "r"(dst), "l"(src))
#define CP_COMMIT() asm volatile("cp.async.commit_group;" ::: "memory")
#define CP_WAIT(n)  asm volatile("cp.async.wait_group %0;" :: "n"(n) : "memory")

// ---------------- block-wide sum over 256 threads ----------------------------
__device__ __forceinline__ float block_sum_256(float v) {
    __shared__ float sh[8];
    int lane = threadIdx.x & 31;
    int wrp  = threadIdx.x >> 5;
    #pragma unroll
    for (int o = 16; o > 0; o >>= 1) v += __shfl_xor_sync(0xffffffffu, v, o);
    if (lane == 0) sh[wrp] = v;
    __syncthreads();
    if (wrp == 0) {
        float t = (lane < 8) ? sh[lane] : 0.0f;
        #pragma unroll
        for (int o = 4; o > 0; o >>= 1) t += __shfl_xor_sync(0xffffffffu, t, o);
        if (lane == 0) sh[0] = t;
    }
    __syncthreads();
    float r = sh[0];
    __syncthreads();
    return r;
}

// ---------------- LayerNorm: h (half) out, optional residual add -------------
template <bool ADD_MEM>
__global__ void ln_kernel(const float* __restrict__ x,
                          const float* __restrict__ mem,
                          const float* __restrict__ w,
                          const float* __restrict__ b,
                          float* __restrict__ xout,
                          __half* __restrict__ hout) {
    const size_t base = (size_t)blockIdx.x * DIM;
    const int tid = threadIdx.x;
    float vals[3];
    #pragma unroll
    for (int i = 0; i < 3; i++) {
        int c = tid + i * 256;
        float xv = x[base + c];
        if (ADD_MEM) { xv += mem[base + c]; xout[base + c] = xv; }
        vals[i] = xv;
    }
    float mu = block_sum_256(vals[0] + vals[1] + vals[2]) * (1.0f / DIM);
    float sq = 0.0f;
    #pragma unroll
    for (int i = 0; i < 3; i++) { float d = vals[i] - mu; sq += d * d; }
    float inv = rsqrtf(block_sum_256(sq) * (1.0f / DIM) + 1e-5f);
    #pragma unroll
    for (int i = 0; i < 3; i++) {
        int c = tid + i * 256;
        hout[base + c] = __float2half_rn((vals[i] - mu) * inv * w[c] + b[c]);
    }
}

// ---------------- f32 -> f16 convert (weights) --------------------------------
__global__ void f2h_kernel(const float* __restrict__ src, __half* __restrict__ dst,
                           size_t n) {
    size_t i = ((size_t)blockIdx.x * 256 + threadIdx.x) * 4;
    if (i + 3 < n) {
        float4 v = *reinterpret_cast<const float4*>(src + i);
        __half2 h0 = __floats2half2_rn(v.x, v.y);
        __half2 h1 = __floats2half2_rn(v.z, v.w);
        *reinterpret_cast<__half2*>(dst + i)     = h0;
        *reinterpret_cast<__half2*>(dst + i + 2) = h1;
    }
}

// ---------------- fp16 wmma GEMM with 4-stage cp.async pipeline ---------------
// C[M,N] = act(A[M,K] @ B[K,N] + bias), A/B half row-major.
// Block tile 256x128, 8 warps (4x2), warp tile 64x64, K-tile 32.
#define BM 256
#define BN 128
#define KT 32
#define NSTAGE 4
#define LDA 40                     // halfs per A smem row (32 + 8 pad)
#define LDB 136                    // halfs per B smem row (128 + 8 pad)
#define A_ST (BM * LDA)            // 10240 halfs
#define B_ST (KT * LDB)            // 4352 halfs
#define ST_HALFS (A_ST + B_ST)     // 14592 halfs = 29184 B
#define SMEM_BYTES (NSTAGE * ST_HALFS * 2)   // 116736 B

#define ACT_NONE 0
#define ACT_SIG  1
#define ACT_GELU 2

template <int ACT, bool ADD_OUT, bool OUT_HALF>
__global__ __launch_bounds__(256)
void gemm_fp16(const __half* __restrict__ A, const __half* __restrict__ B,
               const float* __restrict__ bias, float* __restrict__ Cf,
               __half* __restrict__ Ch, int N, int K) {
    extern __shared__ __align__(16) __half smem[];
    const int tid  = threadIdx.x;
    const int wid  = tid >> 5;
    const int lane = tid & 31;
    const int wm   = wid >> 1;      // 0..3
    const int wn   = wid & 1;       // 0..1

    const int bm = blockIdx.y * BM;
    const int bn = blockIdx.x * BN;
    const int kiters = K / KT;

    const uint32_t smem_base = smem_u32(smem);

    // issue cp.async for stage index ki into buffer buf
    auto load_stage = [&](int buf, int ki) {
        const int k0 = ki * KT;
        const uint32_t stA = smem_base + (uint32_t)buf * ST_HALFS * 2;
        const uint32_t stB = stA + A_ST * 2;
        // A: 256 rows x 32 halfs = 1024 chunks of 16B; 4 per thread
        #pragma unroll
        for (int u = 0; u < 4; u++) {
            int f = tid + u * 256;
            int row = f >> 2, cc = f & 3;
            const __half* src = A + (size_t)(bm + row) * K + k0 + cc * 8;
            CP_ASYNC16(stA + (uint32_t)(row * LDA + cc * 8) * 2, src);
        }
        // B: 32 rows x 128 halfs = 512 chunks; 2 per thread
        #pragma unroll
        for (int u = 0; u < 2; u++) {
            int f = tid + u * 256;
            int row = f >> 4, cc = f & 15;
            const __half* src = B + (size_t)(k0 + row) * N + bn + cc * 8;
            CP_ASYNC16(stB + (uint32_t)(row * LDB + cc * 8) * 2, src);
        }
    };

    wmma::fragment<wmma::accumulator, 16, 16, 16, float> acc[4][4];
    #pragma unroll
    for (int i = 0; i < 4; i++)
        #pragma unroll
        for (int j = 0; j < 4; j++)
            wmma::fill_fragment(acc[i][j], 0.0f);

    // prologue: fill NSTAGE-1 stages
    #pragma unroll
    for (int s = 0; s < NSTAGE - 1; s++) { load_stage(s, s); CP_COMMIT(); }

    for (int ki = 0; ki < kiters; ki++) {
        CP_WAIT(NSTAGE - 2);
        __syncthreads();

        int nxt = ki + NSTAGE - 1;
        if (nxt < kiters) load_stage(nxt % NSTAGE, nxt);
        CP_COMMIT();

        const int buf = ki % NSTAGE;
        const __half* sA = smem + (size_t)buf * ST_HALFS;
        const __half* sB = sA + A_ST;

        #pragma unroll
        for (int kk = 0; kk < KT; kk += 16) {
            wmma::fragment<wmma::matrix_a, 16, 16, 16, __half, wmma::row_major> af[4];
            wmma::fragment<wmma::matrix_b, 16, 16, 16, __half, wmma::row_major> bf[4];
            #pragma unroll
            for (int i = 0; i < 4; i++)
                wmma::load_matrix_sync(af[i], sA + (wm * 64 + i * 16) * LDA + kk, LDA);
            #pragma unroll
            for (int j = 0; j < 4; j++)
                wmma::load_matrix_sync(bf[j], sB + kk * LDB + wn * 64 + j * 16, LDB);
            #pragma unroll
            for (int i = 0; i < 4; i++)
                #pragma unroll
                for (int j = 0; j < 4; j++)
                    wmma::mma_sync(acc[i][j], af[i], bf[j], acc[i][j]);
        }
        __syncthreads();
    }

    // ---------------- epilogue: per-warp smem staging, fused bias/act ---------
    __syncthreads();   // stage buffers are now free for staging reuse
    float* stile = reinterpret_cast<float*>(smem) + (size_t)wid * 32 * 68;

    #pragma unroll
    for (int h = 0; h < 2; h++) {          // two 32-row halves of the 64x64 warp tile
        #pragma unroll
        for (int i2 = 0; i2 < 2; i2++)
            #pragma unroll
            for (int j = 0; j < 4; j++)
                wmma::store_matrix_sync(stile + i2 * 16 * 68 + j * 16,
                                        acc[h * 2 + i2][j], 68, wmma::mem_row_major);
        __syncwarp();
        #pragma unroll
        for (int it = 0; it < 64; it++) {  // 32x64 elems, coalesced
            int idx = it * 32 + lane;
            int row = idx >> 6;
            int col = idx & 63;
            int grow = bm + wm * 64 + h * 32 + row;
            int gcol = bn + wn * 64 + col;
            float val = stile[row * 68 + col] + bias[gcol];
            if (ACT == ACT_SIG)  val = 1.0f / (1.0f + expf(-val));
            if (ACT == ACT_GELU) val = 0.5f * val * (1.0f + erff(val * 0.70710678118654752f));
            const size_t gidx = (size_t)grow * N + gcol;
            if (OUT_HALF) {
                Ch[gidx] = __float2half_rn(val);
            } else {
                if (ADD_OUT) val += Cf[gidx];
                Cf[gidx] = val;
            }
        }
        __syncwarp();
    }
}

// ---------------- chunked normalized cumulative sum --------------------------
__global__ void scan_kernel(const float* __restrict__ G, float* __restrict__ V) {
    const int col   = blockIdx.x * 256 + threadIdx.x;
    const int chunk = blockIdx.y;
    size_t idx = (size_t)chunk * CHUNK * DIM + col;
    float sg = 0.0f, sgv = 0.0f;
    #pragma unroll 4
    for (int t = 0; t < CHUNK; t++) {
        float g = G[idx];
        float v = V[idx];
        sg  += g;
        sgv += g * v;
        V[idx] = sgv / (sg + 1e-6f);
        idx += DIM;
    }
}

// ---------------- launcher ----------------------------------------------------
extern "C" void kernel_launch(void* const* d_in, const int* in_sizes, int n_in,
                              void* d_out, int out_size) {
    const float* x       = (const float*)d_in[0];
    const float* n1w     = (const float*)d_in[1];
    const float* n1b     = (const float*)d_in[2];
    const float* n2w     = (const float*)d_in[3];
    const float* n2b     = (const float*)d_in[4];
    const float* gate_W  = (const float*)d_in[5];
    const float* gate_b  = (const float*)d_in[6];
    const float* value_W = (const float*)d_in[7];
    const float* value_b = (const float*)d_in[8];
    const float* ffn_W1  = (const float*)d_in[9];
    const float* ffn_b1  = (const float*)d_in[10];
    const float* ffn_W2  = (const float*)d_in[11];
    const float* ffn_b2  = (const float*)d_in[12];
    float* out = (float*)d_out;

    __half *h, *ffn, *wg, *wv, *w1, *w2;
    float *g, *v;
    cudaGetSymbolAddress((void**)&h,   g_h);
    cudaGetSymbolAddress((void**)&g,   g_g);
    cudaGetSymbolAddress((void**)&v,   g_v);
    cudaGetSymbolAddress((void**)&ffn, g_ffn);
    cudaGetSymbolAddress((void**)&wg,  g_wg);
    cudaGetSymbolAddress((void**)&wv,  g_wv);
    cudaGetSymbolAddress((void**)&w1,  g_w1);
    cudaGetSymbolAddress((void**)&w2,  g_w2);

    cudaFuncSetAttribute(gemm_fp16<ACT_SIG,  false, false>,
                         cudaFuncAttributeMaxDynamicSharedMemorySize, SMEM_BYTES);
    cudaFuncSetAttribute(gemm_fp16<ACT_NONE, false, false>,
                         cudaFuncAttributeMaxDynamicSharedMemorySize, SMEM_BYTES);
    cudaFuncSetAttribute(gemm_fp16<ACT_GELU, false, true>,
                         cudaFuncAttributeMaxDynamicSharedMemorySize, SMEM_BYTES);
    cudaFuncSetAttribute(gemm_fp16<ACT_NONE, true,  false>,
                         cudaFuncAttributeMaxDynamicSharedMemorySize, SMEM_BYTES);

    // 0. convert weights to half (same [K,N] layout)
    {
        size_t n1 = (size_t)DIM * DIM;
        size_t n2 = (size_t)DIM * DFF;
        f2h_kernel<<<(unsigned)((n1 / 4 + 255) / 256), 256>>>(gate_W,  wg, n1);
        f2h_kernel<<<(unsigned)((n1 / 4 + 255) / 256), 256>>>(value_W, wv, n1);
        f2h_kernel<<<(unsigned)((n2 / 4 + 255) / 256), 256>>>(ffn_W1,  w1, n2);
        f2h_kernel<<<(unsigned)((n2 / 4 + 255) / 256), 256>>>(ffn_W2,  w2, n2);
    }

    // 1. h = LN1(x) (half)
    ln_kernel<false><<<M_ROWS, 256>>>(x, nullptr, n1w, n1b, nullptr, h);

    // 2. g = sigmoid(h @ gate_W + gate_b)   (f32 out)
    gemm_fp16<ACT_SIG, false, false><<<dim3(DIM / BN, M_ROWS / BM), 256, SMEM_BYTES>>>(
        h, wg, gate_b, g, nullptr, DIM, DIM);
    // 3. v = h @ value_W + value_b          (f32 out)
    gemm_fp16<ACT_NONE, false, false><<<dim3(DIM / BN, M_ROWS / BM), 256, SMEM_BYTES>>>(
        h, wv, value_b, v, nullptr, DIM, DIM);
    // 4. v <- mem (chunked normalized cumsum, in place)
    scan_kernel<<<dim3(DIM / 256, NCHUNKS), 256>>>(g, v);
    // 5. out = x + mem ; h = LN2(out) (half)
    ln_kernel<true><<<M_ROWS, 256>>>(x, v, n2w, n2b, out, h);
    // 6. ffn = gelu(h @ W1 + b1)            (half out)
    gemm_fp16<ACT_GELU, false, true><<<dim3(DFF / BN, M_ROWS / BM), 256, SMEM_BYTES>>>(
        h, w1, ffn_b1, nullptr, ffn, DFF, DIM);
    // 7. out += ffn @ W2 + b2               (f32 out, residual)
    gemm_fp16<ACT_NONE, true, false><<<dim3(DIM / BN, M_ROWS / BM), 256, SMEM_BYTES>>>(
        ffn, w2, ffn_b2, out, nullptr, DIM, DFF);
}

// round 5
// speedup vs baseline: 8.0804x; 1.0558x over previous
#include <cuda_runtime.h>
#include <cuda_fp16.h>
#include <mma.h>
#include <math.h>
#include <stdint.h>

using namespace nvcuda;

// Problem constants
#define BATCH   4
#define SEQ     8192
#define DIM     768
#define CHUNK   64
#define M_ROWS  (BATCH * SEQ)       // 32768
#define DFF     (4 * DIM)           // 3072
#define NCHUNKS (M_ROWS / CHUNK)    // 512

// ---------------- scratch (static device globals) ----------------------------
__device__ __half g_h   [(size_t)M_ROWS * DIM];   // LN output (half)
__device__ float  g_g   [(size_t)M_ROWS * DIM];   // gate (f32, scan input)
__device__ float  g_v   [(size_t)M_ROWS * DIM];   // value -> mem (f32)
__device__ __half g_ffn [(size_t)M_ROWS * DFF];   // ffn hidden (half)
__device__ __half g_wg  [(size_t)DIM * DIM];      // gate_W  half [K,N]
__device__ __half g_wv  [(size_t)DIM * DIM];      // value_W half
__device__ __half g_w1  [(size_t)DIM * DFF];      // ffn_W1  half
__device__ __half g_w2  [(size_t)DFF * DIM];      // ffn_W2  half

// ---------------- cp.async helpers -------------------------------------------
__device__ __forceinline__ uint32_t smem_u32(const void* p) {
    uint32_t a;
    asm("{ .reg .u64 t; cvta.to.shared.u64 t, %1; cvt.u32.u64 %0, t; }"
        : "=r"(a) : "l"(p));
    return a;
}
#define CP_ASYNC16(dst, src) \
    asm volatile("cp.async.cg.shared.global [%0], [%1], 16;" :: "r"(dst), "l"(src))
#define CP_COMMIT() asm volatile("cp.async.commit_group;" ::: "memory")
#define CP_WAIT(n)  asm volatile("cp.async.wait_group %0;" :: "n"(n) : "memory")

// ---------------- block-wide sum over 256 threads ----------------------------
__device__ __forceinline__ float block_sum_256(float v) {
    __shared__ float sh[8];
    int lane = threadIdx.x & 31;
    int wrp  = threadIdx.x >> 5;
    #pragma unroll
    for (int o = 16; o > 0; o >>= 1) v += __shfl_xor_sync(0xffffffffu, v, o);
    if (lane == 0) sh[wrp] = v;
    __syncthreads();
    if (wrp == 0) {
        float t = (lane < 8) ? sh[lane] : 0.0f;
        #pragma unroll
        for (int o = 4; o > 0; o >>= 1) t += __shfl_xor_sync(0xffffffffu, t, o);
        if (lane == 0) sh[0] = t;
    }
    __syncthreads();
    float r = sh[0];
    __syncthreads();
    return r;
}

// ---------------- LayerNorm: h (half) out, optional residual add -------------
template <bool ADD_MEM>
__global__ void ln_kernel(const float* __restrict__ x,
                          const float* __restrict__ mem,
                          const float* __restrict__ w,
                          const float* __restrict__ b,
                          float* __restrict__ xout,
                          __half* __restrict__ hout) {
    const size_t base = (size_t)blockIdx.x * DIM;
    const int tid = threadIdx.x;
    float vals[3];
    #pragma unroll
    for (int i = 0; i < 3; i++) {
        int c = tid + i * 256;
        float xv = x[base + c];
        if (ADD_MEM) { xv += mem[base + c]; xout[base + c] = xv; }
        vals[i] = xv;
    }
    float mu = block_sum_256(vals[0] + vals[1] + vals[2]) * (1.0f / DIM);
    float sq = 0.0f;
    #pragma unroll
    for (int i = 0; i < 3; i++) { float d = vals[i] - mu; sq += d * d; }
    float inv = rsqrtf(block_sum_256(sq) * (1.0f / DIM) + 1e-5f);
    #pragma unroll
    for (int i = 0; i < 3; i++) {
        int c = tid + i * 256;
        hout[base + c] = __float2half_rn((vals[i] - mu) * inv * w[c] + b[c]);
    }
}

// ---------------- f32 -> f16 convert (weights) --------------------------------
__global__ void f2h_kernel(const float* __restrict__ src, __half* __restrict__ dst,
                           size_t n) {
    size_t i = ((size_t)blockIdx.x * 256 + threadIdx.x) * 4;
    if (i + 3 < n) {
        float4 v = *reinterpret_cast<const float4*>(src + i);
        __half2 h0 = __floats2half2_rn(v.x, v.y);
        __half2 h1 = __floats2half2_rn(v.z, v.w);
        *reinterpret_cast<__half2*>(dst + i)     = h0;
        *reinterpret_cast<__half2*>(dst + i + 2) = h1;
    }
}

// ---------------- fp16 wmma GEMM, 3-stage cp.async, KT=64, 1 sync/iter -------
// C[M,N] = act(A[M,K] @ B[K,N] + bias), A/B half row-major.
// Block tile 256x128, 8 warps (4x2), warp tile 64x64.
#define BM 256
#define BN 128
#define KT 64
#define NSTAGE 3
#define LDA 72                     // halfs per A smem row (64 + 8 pad)
#define LDB 136                    // halfs per B smem row (128 + 8 pad)
#define A_ST (BM * LDA)            // 18432 halfs
#define B_ST (KT * LDB)            // 8704 halfs
#define ST_HALFS (A_ST + B_ST)     // 27136 halfs = 54272 B
#define SMEM_BYTES (NSTAGE * ST_HALFS * 2)   // 162816 B

#define ACT_NONE 0
#define ACT_SIG  1
#define ACT_GELU 2

template <int ACT, bool ADD_OUT, bool OUT_HALF>
__global__ __launch_bounds__(256)
void gemm_fp16(const __half* __restrict__ A, const __half* __restrict__ B,
               const float* __restrict__ bias, float* __restrict__ Cf,
               __half* __restrict__ Ch, int N, int K) {
    extern __shared__ __align__(16) __half smem[];
    const int tid  = threadIdx.x;
    const int wid  = tid >> 5;
    const int lane = tid & 31;
    const int wm   = wid >> 1;      // 0..3
    const int wn   = wid & 1;       // 0..1

    const int bm = blockIdx.y * BM;
    const int bn = blockIdx.x * BN;
    const int kiters = K / KT;

    const uint32_t smem_base = smem_u32(smem);

    // issue cp.async for K-chunk ki into buffer buf
    auto load_stage = [&](int buf, int ki) {
        const int k0 = ki * KT;
        const uint32_t stA = smem_base + (uint32_t)buf * ST_HALFS * 2;
        const uint32_t stB = stA + A_ST * 2;
        // A: 256 rows x 64 halfs = 2048 chunks of 16B; 8 per thread
        #pragma unroll
        for (int u = 0; u < 8; u++) {
            int f = tid + u * 256;
            int row = f >> 3, cc = f & 7;
            const __half* src = A + (size_t)(bm + row) * K + k0 + cc * 8;
            CP_ASYNC16(stA + (uint32_t)(row * LDA + cc * 8) * 2, src);
        }
        // B: 64 rows x 128 halfs = 1024 chunks; 4 per thread
        #pragma unroll
        for (int u = 0; u < 4; u++) {
            int f = tid + u * 256;
            int row = f >> 4, cc = f & 15;
            const __half* src = B + (size_t)(k0 + row) * N + bn + cc * 8;
            CP_ASYNC16(stB + (uint32_t)(row * LDB + cc * 8) * 2, src);
        }
    };

    wmma::fragment<wmma::accumulator, 16, 16, 16, float> acc[4][4];
    #pragma unroll
    for (int i = 0; i < 4; i++)
        #pragma unroll
        for (int j = 0; j < 4; j++)
            wmma::fill_fragment(acc[i][j], 0.0f);

    // prologue: fill NSTAGE-1 stages
    #pragma unroll
    for (int s = 0; s < NSTAGE - 1; s++) { load_stage(s, s); CP_COMMIT(); }

    for (int ki = 0; ki < kiters; ki++) {
        CP_WAIT(NSTAGE - 2);
        __syncthreads();   // single barrier per iteration:
                           // also provides WAR safety for the load below
                           // (its target buffer was consumed at iter ki-1).

        int nxt = ki + NSTAGE - 1;
        if (nxt < kiters) load_stage(nxt % NSTAGE, nxt);
        CP_COMMIT();

        const int buf = ki % NSTAGE;
        const __half* sA = smem + (size_t)buf * ST_HALFS;
        const __half* sB = sA + A_ST;

        #pragma unroll
        for (int kk = 0; kk < KT; kk += 16) {
            wmma::fragment<wmma::matrix_a, 16, 16, 16, __half, wmma::row_major> af[4];
            wmma::fragment<wmma::matrix_b, 16, 16, 16, __half, wmma::row_major> bf[4];
            #pragma unroll
            for (int i = 0; i < 4; i++)
                wmma::load_matrix_sync(af[i], sA + (wm * 64 + i * 16) * LDA + kk, LDA);
            #pragma unroll
            for (int j = 0; j < 4; j++)
                wmma::load_matrix_sync(bf[j], sB + kk * LDB + wn * 64 + j * 16, LDB);
            #pragma unroll
            for (int i = 0; i < 4; i++)
                #pragma unroll
                for (int j = 0; j < 4; j++)
                    wmma::mma_sync(acc[i][j], af[i], bf[j], acc[i][j]);
        }
        // no trailing sync: next iteration's barrier protects the buffers
    }

    // ---------------- epilogue: per-warp smem staging, fused bias/act ---------
    __syncthreads();   // all compute done; stage buffers free for staging reuse
    float* stile = reinterpret_cast<float*>(smem) + (size_t)wid * 32 * 68;

    #pragma unroll
    for (int h = 0; h < 2; h++) {          // two 32-row halves of the 64x64 warp tile
        #pragma unroll
        for (int i2 = 0; i2 < 2; i2++)
            #pragma unroll
            for (int j = 0; j < 4; j++)
                wmma::store_matrix_sync(stile + i2 * 16 * 68 + j * 16,
                                        acc[h * 2 + i2][j], 68, wmma::mem_row_major);
        __syncwarp();
        #pragma unroll
        for (int it = 0; it < 64; it++) {  // 32x64 elems, coalesced
            int idx = it * 32 + lane;
            int row = idx >> 6;
            int col = idx & 63;
            int grow = bm + wm * 64 + h * 32 + row;
            int gcol = bn + wn * 64 + col;
            float val = stile[row * 68 + col] + bias[gcol];
            if (ACT == ACT_SIG)  val = 1.0f / (1.0f + expf(-val));
            if (ACT == ACT_GELU) val = 0.5f * val * (1.0f + erff(val * 0.70710678118654752f));
            const size_t gidx = (size_t)grow * N + gcol;
            if (OUT_HALF) {
                Ch[gidx] = __float2half_rn(val);
            } else {
                if (ADD_OUT) val += Cf[gidx];
                Cf[gidx] = val;
            }
        }
        __syncwarp();
    }
}

// ---------------- chunked normalized cumulative sum --------------------------
__global__ void scan_kernel(const float* __restrict__ G, float* __restrict__ V) {
    const int col   = blockIdx.x * 256 + threadIdx.x;
    const int chunk = blockIdx.y;
    size_t idx = (size_t)chunk * CHUNK * DIM + col;
    float sg = 0.0f, sgv = 0.0f;
    #pragma unroll 4
    for (int t = 0; t < CHUNK; t++) {
        float g = G[idx];
        float v = V[idx];
        sg  += g;
        sgv += g * v;
        V[idx] = sgv / (sg + 1e-6f);
        idx += DIM;
    }
}

// ---------------- launcher ----------------------------------------------------
extern "C" void kernel_launch(void* const* d_in, const int* in_sizes, int n_in,
                              void* d_out, int out_size) {
    const float* x       = (const float*)d_in[0];
    const float* n1w     = (const float*)d_in[1];
    const float* n1b     = (const float*)d_in[2];
    const float* n2w     = (const float*)d_in[3];
    const float* n2b     = (const float*)d_in[4];
    const float* gate_W  = (const float*)d_in[5];
    const float* gate_b  = (const float*)d_in[6];
    const float* value_W = (const float*)d_in[7];
    const float* value_b = (const float*)d_in[8];
    const float* ffn_W1  = (const float*)d_in[9];
    const float* ffn_b1  = (const float*)d_in[10];
    const float* ffn_W2  = (const float*)d_in[11];
    const float* ffn_b2  = (const float*)d_in[12];
    float* out = (float*)d_out;

    __half *h, *ffn, *wg, *wv, *w1, *w2;
    float *g, *v;
    cudaGetSymbolAddress((void**)&h,   g_h);
    cudaGetSymbolAddress((void**)&g,   g_g);
    cudaGetSymbolAddress((void**)&v,   g_v);
    cudaGetSymbolAddress((void**)&ffn, g_ffn);
    cudaGetSymbolAddress((void**)&wg,  g_wg);
    cudaGetSymbolAddress((void**)&wv,  g_wv);
    cudaGetSymbolAddress((void**)&w1,  g_w1);
    cudaGetSymbolAddress((void**)&w2,  g_w2);

    cudaFuncSetAttribute(gemm_fp16<ACT_SIG,  false, false>,
                         cudaFuncAttributeMaxDynamicSharedMemorySize, SMEM_BYTES);
    cudaFuncSetAttribute(gemm_fp16<ACT_NONE, false, false>,
                         cudaFuncAttributeMaxDynamicSharedMemorySize, SMEM_BYTES);
    cudaFuncSetAttribute(gemm_fp16<ACT_GELU, false, true>,
                         cudaFuncAttributeMaxDynamicSharedMemorySize, SMEM_BYTES);
    cudaFuncSetAttribute(gemm_fp16<ACT_NONE, true,  false>,
                         cudaFuncAttributeMaxDynamicSharedMemorySize, SMEM_BYTES);

    // 0. convert weights to half (same [K,N] layout)
    {
        size_t n1 = (size_t)DIM * DIM;
        size_t n2 = (size_t)DIM * DFF;
        f2h_kernel<<<(unsigned)((n1 / 4 + 255) / 256), 256>>>(gate_W,  wg, n1);
        f2h_kernel<<<(unsigned)((n1 / 4 + 255) / 256), 256>>>(value_W, wv, n1);
        f2h_kernel<<<(unsigned)((n2 / 4 + 255) / 256), 256>>>(ffn_W1,  w1, n2);
        f2h_kernel<<<(unsigned)((n2 / 4 + 255) / 256), 256>>>(ffn_W2,  w2, n2);
    }

    // 1. h = LN1(x) (half)
    ln_kernel<false><<<M_ROWS, 256>>>(x, nullptr, n1w, n1b, nullptr, h);

    // 2. g = sigmoid(h @ gate_W + gate_b)   (f32 out)
    gemm_fp16<ACT_SIG, false, false><<<dim3(DIM / BN, M_ROWS / BM), 256, SMEM_BYTES>>>(
        h, wg, gate_b, g, nullptr, DIM, DIM);
    // 3. v = h @ value_W + value_b          (f32 out)
    gemm_fp16<ACT_NONE, false, false><<<dim3(DIM / BN, M_ROWS / BM), 256, SMEM_BYTES>>>(
        h, wv, value_b, v, nullptr, DIM, DIM);
    // 4. v <- mem (chunked normalized cumsum, in place)
    scan_kernel<<<dim3(DIM / 256, NCHUNKS), 256>>>(g, v);
    // 5. out = x + mem ; h = LN2(out) (half)
    ln_kernel<true><<<M_ROWS, 256>>>(x, v, n2w, n2b, out, h);
    // 6. ffn = gelu(h @ W1 + b1)            (half out)
    gemm_fp16<ACT_GELU, false, true><<<dim3(DFF / BN, M_ROWS / BM), 256, SMEM_BYTES>>>(
        h, w1, ffn_b1, nullptr, ffn, DFF, DIM);
    // 7. out += ffn @ W2 + b2               (f32 out, residual)
    gemm_fp16<ACT_NONE, true, false><<<dim3(DIM / BN, M_ROWS / BM), 256, SMEM_BYTES>>>(
        ffn, w2, ffn_b2, out, nullptr, DIM, DFF);
}

// round 6
// speedup vs baseline: 8.4858x; 1.0502x over previous
#include <cuda_runtime.h>
#include <cuda_fp16.h>
#include <mma.h>
#include <math.h>
#include <stdint.h>

using namespace nvcuda;

// Problem constants
#define BATCH   4
#define SEQ     8192
#define DIM     768
#define CHUNK   64
#define M_ROWS  (BATCH * SEQ)       // 32768
#define DFF     (4 * DIM)           // 3072

// ---------------- scratch (static device globals) ----------------------------
__device__ __half g_h   [(size_t)M_ROWS * DIM];   // LN output (half)
__device__ float  g_mem [(size_t)M_ROWS * DIM];   // scan output (f32)
__device__ __half g_ffn [(size_t)M_ROWS * DFF];   // ffn hidden (half)
__device__ __half g_wg  [(size_t)DIM * DIM];      // gate_W  half [K,N]
__device__ __half g_wv  [(size_t)DIM * DIM];      // value_W half
__device__ __half g_w1  [(size_t)DIM * DFF];      // ffn_W1  half
__device__ __half g_w2  [(size_t)DFF * DIM];      // ffn_W2  half

// ---------------- cp.async helpers -------------------------------------------
__device__ __forceinline__ uint32_t smem_u32(const void* p) {
    uint32_t a;
    asm("{ .reg .u64 t; cvta.to.shared.u64 t, %1; cvt.u32.u64 %0, t; }"
        : "=r"(a) : "l"(p));
    return a;
}
#define CP_ASYNC16(dst, src) \
    asm volatile("cp.async.cg.shared.global [%0], [%1], 16;" :: "r"(dst), "l"(src))
#define CP_COMMIT() asm volatile("cp.async.commit_group;" ::: "memory")
#define CP_WAIT(n)  asm volatile("cp.async.wait_group %0;" :: "n"(n) : "memory")

// ---------------- block-wide sum over 256 threads ----------------------------
__device__ __forceinline__ float block_sum_256(float v) {
    __shared__ float sh[8];
    int lane = threadIdx.x & 31;
    int wrp  = threadIdx.x >> 5;
    #pragma unroll
    for (int o = 16; o > 0; o >>= 1) v += __shfl_xor_sync(0xffffffffu, v, o);
    if (lane == 0) sh[wrp] = v;
    __syncthreads();
    if (wrp == 0) {
        float t = (lane < 8) ? sh[lane] : 0.0f;
        #pragma unroll
        for (int o = 4; o > 0; o >>= 1) t += __shfl_xor_sync(0xffffffffu, t, o);
        if (lane == 0) sh[0] = t;
    }
    __syncthreads();
    float r = sh[0];
    __syncthreads();
    return r;
}

// ---------------- LayerNorm: h (half) out, optional residual add -------------
template <bool ADD_MEM>
__global__ void ln_kernel(const float* __restrict__ x,
                          const float* __restrict__ mem,
                          const float* __restrict__ w,
                          const float* __restrict__ b,
                          float* __restrict__ xout,
                          __half* __restrict__ hout) {
    const size_t base = (size_t)blockIdx.x * DIM;
    const int tid = threadIdx.x;
    float vals[3];
    #pragma unroll
    for (int i = 0; i < 3; i++) {
        int c = tid + i * 256;
        float xv = x[base + c];
        if (ADD_MEM) { xv += mem[base + c]; xout[base + c] = xv; }
        vals[i] = xv;
    }
    float mu = block_sum_256(vals[0] + vals[1] + vals[2]) * (1.0f / DIM);
    float sq = 0.0f;
    #pragma unroll
    for (int i = 0; i < 3; i++) { float d = vals[i] - mu; sq += d * d; }
    float inv = rsqrtf(block_sum_256(sq) * (1.0f / DIM) + 1e-5f);
    #pragma unroll
    for (int i = 0; i < 3; i++) {
        int c = tid + i * 256;
        hout[base + c] = __float2half_rn((vals[i] - mu) * inv * w[c] + b[c]);
    }
}

// ---------------- f32 -> f16 convert (weights) --------------------------------
__global__ void f2h_kernel(const float* __restrict__ src, __half* __restrict__ dst,
                           size_t n) {
    size_t i = ((size_t)blockIdx.x * 256 + threadIdx.x) * 4;
    if (i + 3 < n) {
        float4 v = *reinterpret_cast<const float4*>(src + i);
        __half2 h0 = __floats2half2_rn(v.x, v.y);
        __half2 h1 = __floats2half2_rn(v.z, v.w);
        *reinterpret_cast<__half2*>(dst + i)     = h0;
        *reinterpret_cast<__half2*>(dst + i + 2) = h1;
    }
}

// =============== Fused gate+value GEMM + chunked scan =========================
// Computes g = sigmoid(h@Wg + bg), v = h@Wv + bv for a 256x64 tile, then runs
// the chunked normalized cumsum in the epilogue (warp M-tile == CHUNK == 64)
// and writes mem directly. A is streamed once for both GEMMs.
#define GBM 256
#define GBN 64
#define GKT 64
#define GLDA 72
#define GLDB 72
#define GA_ST (GBM * GLDA)              // 18432 halfs
#define GB_ST (GKT * GLDB)              // 4608 halfs (per weight matrix)
#define GST_HALFS (GA_ST + 2 * GB_ST)   // 27648 halfs = 55296 B
#define GSMEM_BYTES (3 * GST_HALFS * 2) // 165888 B

__global__ __launch_bounds__(256)
void gemm_gv_scan(const __half* __restrict__ A, const __half* __restrict__ Wg,
                  const __half* __restrict__ Wv,
                  const float* __restrict__ gate_b,
                  const float* __restrict__ value_b,
                  float* __restrict__ mem_out) {
    extern __shared__ __align__(16) __half smem[];
    const int tid  = threadIdx.x;
    const int wid  = tid >> 5;
    const int lane = tid & 31;
    const int wm   = wid >> 1;      // 0..3 -> 64-row chunk
    const int wn   = wid & 1;       // 0..1 -> 32-col half

    const int bm = blockIdx.y * GBM;
    const int bn = blockIdx.x * GBN;
    const int K = DIM, N = DIM;
    const int kiters = K / GKT;     // 12

    const uint32_t smem_base = smem_u32(smem);

    auto load_stage = [&](int buf, int ki) {
        const int k0 = ki * GKT;
        const uint32_t stA  = smem_base + (uint32_t)buf * GST_HALFS * 2;
        const uint32_t stBg = stA + GA_ST * 2;
        const uint32_t stBv = stBg + GB_ST * 2;
        // A: 256 x 64 halfs = 2048 chunks of 16B; 8 per thread
        #pragma unroll
        for (int u = 0; u < 8; u++) {
            int f = tid + u * 256;
            int row = f >> 3, cc = f & 7;
            CP_ASYNC16(stA + (uint32_t)(row * GLDA + cc * 8) * 2,
                       A + (size_t)(bm + row) * K + k0 + cc * 8);
        }
        // Bg, Bv: 64 x 64 halfs = 512 chunks each; 2 per thread each
        #pragma unroll
        for (int u = 0; u < 2; u++) {
            int f = tid + u * 256;
            int row = f >> 3, cc = f & 7;
            CP_ASYNC16(stBg + (uint32_t)(row * GLDB + cc * 8) * 2,
                       Wg + (size_t)(k0 + row) * N + bn + cc * 8);
            CP_ASYNC16(stBv + (uint32_t)(row * GLDB + cc * 8) * 2,
                       Wv + (size_t)(k0 + row) * N + bn + cc * 8);
        }
    };

    wmma::fragment<wmma::accumulator, 16, 16, 16, float> accg[4][2], accv[4][2];
    #pragma unroll
    for (int i = 0; i < 4; i++)
        #pragma unroll
        for (int j = 0; j < 2; j++) {
            wmma::fill_fragment(accg[i][j], 0.0f);
            wmma::fill_fragment(accv[i][j], 0.0f);
        }

    #pragma unroll
    for (int s = 0; s < 2; s++) { load_stage(s, s); CP_COMMIT(); }

    for (int ki = 0; ki < kiters; ki++) {
        CP_WAIT(1);
        __syncthreads();

        int nxt = ki + 2;
        if (nxt < kiters) load_stage(nxt % 3, nxt);
        CP_COMMIT();

        const int buf = ki % 3;
        const __half* sA  = smem + (size_t)buf * GST_HALFS;
        const __half* sBg = sA + GA_ST;
        const __half* sBv = sBg + GB_ST;

        #pragma unroll
        for (int kk = 0; kk < GKT; kk += 16) {
            wmma::fragment<wmma::matrix_a, 16, 16, 16, __half, wmma::row_major> af[4];
            wmma::fragment<wmma::matrix_b, 16, 16, 16, __half, wmma::row_major> bgf[2], bvf[2];
            #pragma unroll
            for (int i = 0; i < 4; i++)
                wmma::load_matrix_sync(af[i], sA + (wm * 64 + i * 16) * GLDA + kk, GLDA);
            #pragma unroll
            for (int j = 0; j < 2; j++) {
                wmma::load_matrix_sync(bgf[j], sBg + kk * GLDB + wn * 32 + j * 16, GLDB);
                wmma::load_matrix_sync(bvf[j], sBv + kk * GLDB + wn * 32 + j * 16, GLDB);
            }
            #pragma unroll
            for (int i = 0; i < 4; i++)
                #pragma unroll
                for (int j = 0; j < 2; j++) {
                    wmma::mma_sync(accg[i][j], af[i], bgf[j], accg[i][j]);
                    wmma::mma_sync(accv[i][j], af[i], bvf[j], accv[i][j]);
                }
        }
    }

    // ---------------- epilogue: stage + per-column chunked scan ---------------
    __syncthreads();
    float* gt = reinterpret_cast<float*>(smem) + (size_t)wid * (2 * 64 * 36);
    float* vt = gt + 64 * 36;
    #pragma unroll
    for (int i = 0; i < 4; i++)
        #pragma unroll
        for (int j = 0; j < 2; j++) {
            wmma::store_matrix_sync(gt + i * 16 * 36 + j * 16, accg[i][j], 36,
                                    wmma::mem_row_major);
            wmma::store_matrix_sync(vt + i * 16 * 36 + j * 16, accv[i][j], 36,
                                    wmma::mem_row_major);
        }
    __syncwarp();

    // Each lane owns one feature column; warp rows == one CHUNK (64) exactly.
    const int gcol = bn + wn * 32 + lane;
    const float bg = gate_b[gcol];
    const float bv = value_b[gcol];
    float sg = 0.0f, sgv = 0.0f;
    const size_t rbase = (size_t)(bm + wm * 64) * DIM + gcol;
    #pragma unroll 4
    for (int r = 0; r < 64; r++) {
        float gval = gt[r * 36 + lane] + bg;
        gval = 1.0f / (1.0f + expf(-gval));
        float vval = vt[r * 36 + lane] + bv;
        sg  += gval;
        sgv += gval * vval;
        mem_out[rbase + (size_t)r * DIM] = sgv / (sg + 1e-6f);
    }
}

// ---------------- fp16 wmma GEMM, 3-stage cp.async, KT=64 (FFN path) ---------
#define BM 256
#define BN 128
#define KT 64
#define NSTAGE 3
#define LDA 72
#define LDB 136
#define A_ST (BM * LDA)
#define B_ST (KT * LDB)
#define ST_HALFS (A_ST + B_ST)
#define SMEM_BYTES (NSTAGE * ST_HALFS * 2)   // 162816 B

#define ACT_NONE 0
#define ACT_GELU 2

template <int ACT, bool ADD_OUT, bool OUT_HALF>
__global__ __launch_bounds__(256)
void gemm_fp16(const __half* __restrict__ A, const __half* __restrict__ B,
               const float* __restrict__ bias, float* __restrict__ Cf,
               __half* __restrict__ Ch, int N, int K) {
    extern __shared__ __align__(16) __half smem[];
    const int tid  = threadIdx.x;
    const int wid  = tid >> 5;
    const int lane = tid & 31;
    const int wm   = wid >> 1;
    const int wn   = wid & 1;

    const int bm = blockIdx.y * BM;
    const int bn = blockIdx.x * BN;
    const int kiters = K / KT;

    const uint32_t smem_base = smem_u32(smem);

    auto load_stage = [&](int buf, int ki) {
        const int k0 = ki * KT;
        const uint32_t stA = smem_base + (uint32_t)buf * ST_HALFS * 2;
        const uint32_t stB = stA + A_ST * 2;
        #pragma unroll
        for (int u = 0; u < 8; u++) {
            int f = tid + u * 256;
            int row = f >> 3, cc = f & 7;
            CP_ASYNC16(stA + (uint32_t)(row * LDA + cc * 8) * 2,
                       A + (size_t)(bm + row) * K + k0 + cc * 8);
        }
        #pragma unroll
        for (int u = 0; u < 4; u++) {
            int f = tid + u * 256;
            int row = f >> 4, cc = f & 15;
            CP_ASYNC16(stB + (uint32_t)(row * LDB + cc * 8) * 2,
                       B + (size_t)(k0 + row) * N + bn + cc * 8);
        }
    };

    wmma::fragment<wmma::accumulator, 16, 16, 16, float> acc[4][4];
    #pragma unroll
    for (int i = 0; i < 4; i++)
        #pragma unroll
        for (int j = 0; j < 4; j++)
            wmma::fill_fragment(acc[i][j], 0.0f);

    #pragma unroll
    for (int s = 0; s < NSTAGE - 1; s++) { load_stage(s, s); CP_COMMIT(); }

    for (int ki = 0; ki < kiters; ki++) {
        CP_WAIT(NSTAGE - 2);
        __syncthreads();

        int nxt = ki + NSTAGE - 1;
        if (nxt < kiters) load_stage(nxt % NSTAGE, nxt);
        CP_COMMIT();

        const int buf = ki % NSTAGE;
        const __half* sA = smem + (size_t)buf * ST_HALFS;
        const __half* sB = sA + A_ST;

        #pragma unroll
        for (int kk = 0; kk < KT; kk += 16) {
            wmma::fragment<wmma::matrix_a, 16, 16, 16, __half, wmma::row_major> af[4];
            wmma::fragment<wmma::matrix_b, 16, 16, 16, __half, wmma::row_major> bf[4];
            #pragma unroll
            for (int i = 0; i < 4; i++)
                wmma::load_matrix_sync(af[i], sA + (wm * 64 + i * 16) * LDA + kk, LDA);
            #pragma unroll
            for (int j = 0; j < 4; j++)
                wmma::load_matrix_sync(bf[j], sB + kk * LDB + wn * 64 + j * 16, LDB);
            #pragma unroll
            for (int i = 0; i < 4; i++)
                #pragma unroll
                for (int j = 0; j < 4; j++)
                    wmma::mma_sync(acc[i][j], af[i], bf[j], acc[i][j]);
        }
    }

    __syncthreads();
    float* stile = reinterpret_cast<float*>(smem) + (size_t)wid * 32 * 68;

    #pragma unroll
    for (int h = 0; h < 2; h++) {
        #pragma unroll
        for (int i2 = 0; i2 < 2; i2++)
            #pragma unroll
            for (int j = 0; j < 4; j++)
                wmma::store_matrix_sync(stile + i2 * 16 * 68 + j * 16,
                                        acc[h * 2 + i2][j], 68, wmma::mem_row_major);
        __syncwarp();
        #pragma unroll
        for (int it = 0; it < 64; it++) {
            int idx = it * 32 + lane;
            int row = idx >> 6;
            int col = idx & 63;
            int grow = bm + wm * 64 + h * 32 + row;
            int gcol = bn + wn * 64 + col;
            float val = stile[row * 68 + col] + bias[gcol];
            if (ACT == ACT_GELU) val = 0.5f * val * (1.0f + erff(val * 0.70710678118654752f));
            const size_t gidx = (size_t)grow * N + gcol;
            if (OUT_HALF) {
                Ch[gidx] = __float2half_rn(val);
            } else {
                if (ADD_OUT) val += Cf[gidx];
                Cf[gidx] = val;
            }
        }
        __syncwarp();
    }
}

// ---------------- launcher ----------------------------------------------------
extern "C" void kernel_launch(void* const* d_in, const int* in_sizes, int n_in,
                              void* d_out, int out_size) {
    const float* x       = (const float*)d_in[0];
    const float* n1w     = (const float*)d_in[1];
    const float* n1b     = (const float*)d_in[2];
    const float* n2w     = (const float*)d_in[3];
    const float* n2b     = (const float*)d_in[4];
    const float* gate_W  = (const float*)d_in[5];
    const float* gate_b  = (const float*)d_in[6];
    const float* value_W = (const float*)d_in[7];
    const float* value_b = (const float*)d_in[8];
    const float* ffn_W1  = (const float*)d_in[9];
    const float* ffn_b1  = (const float*)d_in[10];
    const float* ffn_W2  = (const float*)d_in[11];
    const float* ffn_b2  = (const float*)d_in[12];
    float* out = (float*)d_out;

    __half *h, *ffn, *wg, *wv, *w1, *w2;
    float *mem;
    cudaGetSymbolAddress((void**)&h,   g_h);
    cudaGetSymbolAddress((void**)&mem, g_mem);
    cudaGetSymbolAddress((void**)&ffn, g_ffn);
    cudaGetSymbolAddress((void**)&wg,  g_wg);
    cudaGetSymbolAddress((void**)&wv,  g_wv);
    cudaGetSymbolAddress((void**)&w1,  g_w1);
    cudaGetSymbolAddress((void**)&w2,  g_w2);

    cudaFuncSetAttribute(gemm_gv_scan,
                         cudaFuncAttributeMaxDynamicSharedMemorySize, GSMEM_BYTES);
    cudaFuncSetAttribute(gemm_fp16<ACT_GELU, false, true>,
                         cudaFuncAttributeMaxDynamicSharedMemorySize, SMEM_BYTES);
    cudaFuncSetAttribute(gemm_fp16<ACT_NONE, true,  false>,
                         cudaFuncAttributeMaxDynamicSharedMemorySize, SMEM_BYTES);

    // 0. convert weights to half
    {
        size_t n1 = (size_t)DIM * DIM;
        size_t n2 = (size_t)DIM * DFF;
        f2h_kernel<<<(unsigned)((n1 / 4 + 255) / 256), 256>>>(gate_W,  wg, n1);
        f2h_kernel<<<(unsigned)((n1 / 4 + 255) / 256), 256>>>(value_W, wv, n1);
        f2h_kernel<<<(unsigned)((n2 / 4 + 255) / 256), 256>>>(ffn_W1,  w1, n2);
        f2h_kernel<<<(unsigned)((n2 / 4 + 255) / 256), 256>>>(ffn_W2,  w2, n2);
    }

    // 1. h = LN1(x) (half)
    ln_kernel<false><<<M_ROWS, 256>>>(x, nullptr, n1w, n1b, nullptr, h);

    // 2+3+4 fused: mem = chunked_scan(sigmoid(h@Wg+bg), h@Wv+bv)
    gemm_gv_scan<<<dim3(DIM / GBN, M_ROWS / GBM), 256, GSMEM_BYTES>>>(
        h, wg, wv, gate_b, value_b, mem);

    // 5. out = x + mem ; h = LN2(out) (half)
    ln_kernel<true><<<M_ROWS, 256>>>(x, mem, n2w, n2b, out, h);

    // 6. ffn = gelu(h @ W1 + b1)            (half out)
    gemm_fp16<ACT_GELU, false, true><<<dim3(DFF / BN, M_ROWS / BM), 256, SMEM_BYTES>>>(
        h, w1, ffn_b1, nullptr, ffn, DFF, DIM);
    // 7. out += ffn @ W2 + b2               (f32 out, residual)
    gemm_fp16<ACT_NONE, true, false><<<dim3(DIM / BN, M_ROWS / BM), 256, SMEM_BYTES>>>(
        ffn, w2, ffn_b2, out, nullptr, DIM, DFF);
}

// round 7
// speedup vs baseline: 8.9836x; 1.0587x over previous
#include <cuda_runtime.h>
#include <cuda_fp16.h>
#include <mma.h>
#include <math.h>
#include <stdint.h>

using namespace nvcuda;

// Problem constants
#define BATCH   4
#define SEQ     8192
#define DIM     768
#define CHUNK   64
#define M_ROWS  (BATCH * SEQ)       // 32768
#define DFF     (4 * DIM)           // 3072

// ---------------- scratch (static device globals) ----------------------------
__device__ __half g_h   [(size_t)M_ROWS * DIM];   // LN output (half)
__device__ float  g_mem [(size_t)M_ROWS * DIM];   // scan output (f32)
__device__ __half g_ffn [(size_t)M_ROWS * DFF];   // ffn hidden (half)
__device__ __half g_wg  [(size_t)DIM * DIM];      // gate_W  half [K,N]
__device__ __half g_wv  [(size_t)DIM * DIM];      // value_W half
__device__ __half g_w1  [(size_t)DIM * DFF];      // ffn_W1  half
__device__ __half g_w2  [(size_t)DFF * DIM];      // ffn_W2  half

// ---------------- cp.async helpers -------------------------------------------
__device__ __forceinline__ uint32_t smem_u32(const void* p) {
    uint32_t a;
    asm("{ .reg .u64 t; cvta.to.shared.u64 t, %1; cvt.u32.u64 %0, t; }"
        : "=r"(a) : "l"(p));
    return a;
}
#define CP_ASYNC16(dst, src) \
    asm volatile("cp.async.cg.shared.global [%0], [%1], 16;" :: "r"(dst), "l"(src))
#define CP_COMMIT() asm volatile("cp.async.commit_group;" ::: "memory")
#define CP_WAIT(n)  asm volatile("cp.async.wait_group %0;" :: "n"(n) : "memory")

// ---------------- block-wide sum over 256 threads ----------------------------
__device__ __forceinline__ float block_sum_256(float v) {
    __shared__ float sh[8];
    int lane = threadIdx.x & 31;
    int wrp  = threadIdx.x >> 5;
    #pragma unroll
    for (int o = 16; o > 0; o >>= 1) v += __shfl_xor_sync(0xffffffffu, v, o);
    if (lane == 0) sh[wrp] = v;
    __syncthreads();
    if (wrp == 0) {
        float t = (lane < 8) ? sh[lane] : 0.0f;
        #pragma unroll
        for (int o = 4; o > 0; o >>= 1) t += __shfl_xor_sync(0xffffffffu, t, o);
        if (lane == 0) sh[0] = t;
    }
    __syncthreads();
    float r = sh[0];
    __syncthreads();
    return r;
}

// ---------------- LayerNorm: h (half) out, optional residual add -------------
template <bool ADD_MEM>
__global__ void ln_kernel(const float* __restrict__ x,
                          const float* __restrict__ mem,
                          const float* __restrict__ w,
                          const float* __restrict__ b,
                          float* __restrict__ xout,
                          __half* __restrict__ hout) {
    const size_t base = (size_t)blockIdx.x * DIM;
    const int tid = threadIdx.x;
    float vals[3];
    #pragma unroll
    for (int i = 0; i < 3; i++) {
        int c = tid + i * 256;
        float xv = x[base + c];
        if (ADD_MEM) { xv += mem[base + c]; xout[base + c] = xv; }
        vals[i] = xv;
    }
    float mu = block_sum_256(vals[0] + vals[1] + vals[2]) * (1.0f / DIM);
    float sq = 0.0f;
    #pragma unroll
    for (int i = 0; i < 3; i++) { float d = vals[i] - mu; sq += d * d; }
    float inv = rsqrtf(block_sum_256(sq) * (1.0f / DIM) + 1e-5f);
    #pragma unroll
    for (int i = 0; i < 3; i++) {
        int c = tid + i * 256;
        hout[base + c] = __float2half_rn((vals[i] - mu) * inv * w[c] + b[c]);
    }
}

// ---------------- f32 -> f16 convert (weights) --------------------------------
__global__ void f2h_kernel(const float* __restrict__ src, __half* __restrict__ dst,
                           size_t n) {
    size_t i = ((size_t)blockIdx.x * 256 + threadIdx.x) * 4;
    if (i + 3 < n) {
        float4 v = *reinterpret_cast<const float4*>(src + i);
        __half2 h0 = __floats2half2_rn(v.x, v.y);
        __half2 h1 = __floats2half2_rn(v.z, v.w);
        *reinterpret_cast<__half2*>(dst + i)     = h0;
        *reinterpret_cast<__half2*>(dst + i + 2) = h1;
    }
}

// =============== Fused gate+value GEMM + chunked scan (unchanged R6) ==========
#define GBM 256
#define GBN 64
#define GKT 64
#define GLDA 72
#define GLDB 72
#define GA_ST (GBM * GLDA)              // 18432 halfs
#define GB_ST (GKT * GLDB)              // 4608 halfs (per weight matrix)
#define GST_HALFS (GA_ST + 2 * GB_ST)   // 27648 halfs = 55296 B
#define GSMEM_BYTES (3 * GST_HALFS * 2) // 165888 B

__global__ __launch_bounds__(256)
void gemm_gv_scan(const __half* __restrict__ A, const __half* __restrict__ Wg,
                  const __half* __restrict__ Wv,
                  const float* __restrict__ gate_b,
                  const float* __restrict__ value_b,
                  float* __restrict__ mem_out) {
    extern __shared__ __align__(16) __half smem[];
    const int tid  = threadIdx.x;
    const int wid  = tid >> 5;
    const int lane = tid & 31;
    const int wm   = wid >> 1;      // 0..3 -> 64-row chunk
    const int wn   = wid & 1;       // 0..1 -> 32-col half

    const int bm = blockIdx.y * GBM;
    const int bn = blockIdx.x * GBN;
    const int K = DIM, N = DIM;
    const int kiters = K / GKT;     // 12

    const uint32_t smem_base = smem_u32(smem);

    auto load_stage = [&](int buf, int ki) {
        const int k0 = ki * GKT;
        const uint32_t stA  = smem_base + (uint32_t)buf * GST_HALFS * 2;
        const uint32_t stBg = stA + GA_ST * 2;
        const uint32_t stBv = stBg + GB_ST * 2;
        #pragma unroll
        for (int u = 0; u < 8; u++) {
            int f = tid + u * 256;
            int row = f >> 3, cc = f & 7;
            CP_ASYNC16(stA + (uint32_t)(row * GLDA + cc * 8) * 2,
                       A + (size_t)(bm + row) * K + k0 + cc * 8);
        }
        #pragma unroll
        for (int u = 0; u < 2; u++) {
            int f = tid + u * 256;
            int row = f >> 3, cc = f & 7;
            CP_ASYNC16(stBg + (uint32_t)(row * GLDB + cc * 8) * 2,
                       Wg + (size_t)(k0 + row) * N + bn + cc * 8);
            CP_ASYNC16(stBv + (uint32_t)(row * GLDB + cc * 8) * 2,
                       Wv + (size_t)(k0 + row) * N + bn + cc * 8);
        }
    };

    wmma::fragment<wmma::accumulator, 16, 16, 16, float> accg[4][2], accv[4][2];
    #pragma unroll
    for (int i = 0; i < 4; i++)
        #pragma unroll
        for (int j = 0; j < 2; j++) {
            wmma::fill_fragment(accg[i][j], 0.0f);
            wmma::fill_fragment(accv[i][j], 0.0f);
        }

    #pragma unroll
    for (int s = 0; s < 2; s++) { load_stage(s, s); CP_COMMIT(); }

    for (int ki = 0; ki < kiters; ki++) {
        CP_WAIT(1);
        __syncthreads();

        int nxt = ki + 2;
        if (nxt < kiters) load_stage(nxt % 3, nxt);
        CP_COMMIT();

        const int buf = ki % 3;
        const __half* sA  = smem + (size_t)buf * GST_HALFS;
        const __half* sBg = sA + GA_ST;
        const __half* sBv = sBg + GB_ST;

        #pragma unroll
        for (int kk = 0; kk < GKT; kk += 16) {
            wmma::fragment<wmma::matrix_a, 16, 16, 16, __half, wmma::row_major> af[4];
            wmma::fragment<wmma::matrix_b, 16, 16, 16, __half, wmma::row_major> bgf[2], bvf[2];
            #pragma unroll
            for (int i = 0; i < 4; i++)
                wmma::load_matrix_sync(af[i], sA + (wm * 64 + i * 16) * GLDA + kk, GLDA);
            #pragma unroll
            for (int j = 0; j < 2; j++) {
                wmma::load_matrix_sync(bgf[j], sBg + kk * GLDB + wn * 32 + j * 16, GLDB);
                wmma::load_matrix_sync(bvf[j], sBv + kk * GLDB + wn * 32 + j * 16, GLDB);
            }
            #pragma unroll
            for (int i = 0; i < 4; i++)
                #pragma unroll
                for (int j = 0; j < 2; j++) {
                    wmma::mma_sync(accg[i][j], af[i], bgf[j], accg[i][j]);
                    wmma::mma_sync(accv[i][j], af[i], bvf[j], accv[i][j]);
                }
        }
    }

    __syncthreads();
    float* gt = reinterpret_cast<float*>(smem) + (size_t)wid * (2 * 64 * 36);
    float* vt = gt + 64 * 36;
    #pragma unroll
    for (int i = 0; i < 4; i++)
        #pragma unroll
        for (int j = 0; j < 2; j++) {
            wmma::store_matrix_sync(gt + i * 16 * 36 + j * 16, accg[i][j], 36,
                                    wmma::mem_row_major);
            wmma::store_matrix_sync(vt + i * 16 * 36 + j * 16, accv[i][j], 36,
                                    wmma::mem_row_major);
        }
    __syncwarp();

    const int gcol = bn + wn * 32 + lane;
    const float bg = gate_b[gcol];
    const float bv = value_b[gcol];
    float sg = 0.0f, sgv = 0.0f;
    const size_t rbase = (size_t)(bm + wm * 64) * DIM + gcol;
    #pragma unroll 4
    for (int r = 0; r < 64; r++) {
        float gval = gt[r * 36 + lane] + bg;
        gval = 1.0f / (1.0f + expf(-gval));
        float vval = vt[r * 36 + lane] + bv;
        sg  += gval;
        sgv += gval * vval;
        mem_out[rbase + (size_t)r * DIM] = sgv / (sg + 1e-6f);
    }
}

// ---------------- FFN GEMM: 512 threads, 16 warps, warp tile 64x32 ------------
#define BM 256
#define BN 128
#define KT 64
#define NSTAGE 3
#define LDA 72
#define LDB 136
#define A_ST (BM * LDA)
#define B_ST (KT * LDB)
#define ST_HALFS (A_ST + B_ST)
#define SMEM_BYTES (NSTAGE * ST_HALFS * 2)   // 162816 B
#define NTHREADS 512

#define ACT_NONE 0
#define ACT_GELU 2

template <int ACT, bool ADD_OUT, bool OUT_HALF>
__global__ __launch_bounds__(NTHREADS, 1)
void gemm_fp16(const __half* __restrict__ A, const __half* __restrict__ B,
               const float* __restrict__ bias, float* __restrict__ Cf,
               __half* __restrict__ Ch, int N, int K) {
    extern __shared__ __align__(16) __half smem[];
    const int tid  = threadIdx.x;
    const int wid  = tid >> 5;      // 0..15
    const int lane = tid & 31;
    const int wm   = wid >> 2;      // 0..3 -> 64-row band
    const int wn   = wid & 3;       // 0..3 -> 32-col band

    const int bm = blockIdx.y * BM;
    const int bn = blockIdx.x * BN;
    const int kiters = K / KT;

    const uint32_t smem_base = smem_u32(smem);

    auto load_stage = [&](int buf, int ki) {
        const int k0 = ki * KT;
        const uint32_t stA = smem_base + (uint32_t)buf * ST_HALFS * 2;
        const uint32_t stB = stA + A_ST * 2;
        // A: 256 x 64 halfs = 2048 16B-chunks; 4 per thread
        #pragma unroll
        for (int u = 0; u < 4; u++) {
            int f = tid + u * NTHREADS;
            int row = f >> 3, cc = f & 7;
            CP_ASYNC16(stA + (uint32_t)(row * LDA + cc * 8) * 2,
                       A + (size_t)(bm + row) * K + k0 + cc * 8);
        }
        // B: 64 x 128 halfs = 1024 chunks; 2 per thread
        #pragma unroll
        for (int u = 0; u < 2; u++) {
            int f = tid + u * NTHREADS;
            int row = f >> 4, cc = f & 15;
            CP_ASYNC16(stB + (uint32_t)(row * LDB + cc * 8) * 2,
                       B + (size_t)(k0 + row) * N + bn + cc * 8);
        }
    };

    wmma::fragment<wmma::accumulator, 16, 16, 16, float> acc[4][2];
    #pragma unroll
    for (int i = 0; i < 4; i++)
        #pragma unroll
        for (int j = 0; j < 2; j++)
            wmma::fill_fragment(acc[i][j], 0.0f);

    #pragma unroll
    for (int s = 0; s < NSTAGE - 1; s++) { load_stage(s, s); CP_COMMIT(); }

    for (int ki = 0; ki < kiters; ki++) {
        CP_WAIT(NSTAGE - 2);
        __syncthreads();

        int nxt = ki + NSTAGE - 1;
        if (nxt < kiters) load_stage(nxt % NSTAGE, nxt);
        CP_COMMIT();

        const int buf = ki % NSTAGE;
        const __half* sA = smem + (size_t)buf * ST_HALFS;
        const __half* sB = sA + A_ST;

        #pragma unroll
        for (int kk = 0; kk < KT; kk += 16) {
            wmma::fragment<wmma::matrix_a, 16, 16, 16, __half, wmma::row_major> af[4];
            wmma::fragment<wmma::matrix_b, 16, 16, 16, __half, wmma::row_major> bf[2];
            #pragma unroll
            for (int i = 0; i < 4; i++)
                wmma::load_matrix_sync(af[i], sA + (wm * 64 + i * 16) * LDA + kk, LDA);
            #pragma unroll
            for (int j = 0; j < 2; j++)
                wmma::load_matrix_sync(bf[j], sB + kk * LDB + wn * 32 + j * 16, LDB);
            #pragma unroll
            for (int i = 0; i < 4; i++)
                #pragma unroll
                for (int j = 0; j < 2; j++)
                    wmma::mma_sync(acc[i][j], af[i], bf[j], acc[i][j]);
        }
    }

    // ---------------- epilogue: per-warp smem staging, fused bias/act ---------
    __syncthreads();
    float* stile = reinterpret_cast<float*>(smem) + (size_t)wid * 32 * 36;

    #pragma unroll
    for (int h = 0; h < 2; h++) {          // two 32-row halves of the 64x32 warp tile
        #pragma unroll
        for (int j = 0; j < 2; j++)
            wmma::store_matrix_sync(stile + j * 16,
                                    acc[h * 2 + 0][j], 36, wmma::mem_row_major);
        #pragma unroll
        for (int j = 0; j < 2; j++)
            wmma::store_matrix_sync(stile + 16 * 36 + j * 16,
                                    acc[h * 2 + 1][j], 36, wmma::mem_row_major);
        __syncwarp();
        #pragma unroll
        for (int it = 0; it < 32; it++) {  // 32x32 elems, coalesced
            int idx = it * 32 + lane;
            int row = idx >> 5;
            int col = idx & 31;
            int grow = bm + wm * 64 + h * 32 + row;
            int gcol = bn + wn * 32 + col;
            float val = stile[row * 36 + col] + bias[gcol];
            if (ACT == ACT_GELU) val = 0.5f * val * (1.0f + erff(val * 0.70710678118654752f));
            const size_t gidx = (size_t)grow * N + gcol;
            if (OUT_HALF) {
                Ch[gidx] = __float2half_rn(val);
            } else {
                if (ADD_OUT) val += Cf[gidx];
                Cf[gidx] = val;
            }
        }
        __syncwarp();
    }
}

// ---------------- launcher ----------------------------------------------------
extern "C" void kernel_launch(void* const* d_in, const int* in_sizes, int n_in,
                              void* d_out, int out_size) {
    const float* x       = (const float*)d_in[0];
    const float* n1w     = (const float*)d_in[1];
    const float* n1b     = (const float*)d_in[2];
    const float* n2w     = (const float*)d_in[3];
    const float* n2b     = (const float*)d_in[4];
    const float* gate_W  = (const float*)d_in[5];
    const float* gate_b  = (const float*)d_in[6];
    const float* value_W = (const float*)d_in[7];
    const float* value_b = (const float*)d_in[8];
    const float* ffn_W1  = (const float*)d_in[9];
    const float* ffn_b1  = (const float*)d_in[10];
    const float* ffn_W2  = (const float*)d_in[11];
    const float* ffn_b2  = (const float*)d_in[12];
    float* out = (float*)d_out;

    __half *h, *ffn, *wg, *wv, *w1, *w2;
    float *mem;
    cudaGetSymbolAddress((void**)&h,   g_h);
    cudaGetSymbolAddress((void**)&mem, g_mem);
    cudaGetSymbolAddress((void**)&ffn, g_ffn);
    cudaGetSymbolAddress((void**)&wg,  g_wg);
    cudaGetSymbolAddress((void**)&wv,  g_wv);
    cudaGetSymbolAddress((void**)&w1,  g_w1);
    cudaGetSymbolAddress((void**)&w2,  g_w2);

    cudaFuncSetAttribute(gemm_gv_scan,
                         cudaFuncAttributeMaxDynamicSharedMemorySize, GSMEM_BYTES);
    cudaFuncSetAttribute(gemm_fp16<ACT_GELU, false, true>,
                         cudaFuncAttributeMaxDynamicSharedMemorySize, SMEM_BYTES);
    cudaFuncSetAttribute(gemm_fp16<ACT_NONE, true,  false>,
                         cudaFuncAttributeMaxDynamicSharedMemorySize, SMEM_BYTES);

    // 0. convert weights to half
    {
        size_t n1 = (size_t)DIM * DIM;
        size_t n2 = (size_t)DIM * DFF;
        f2h_kernel<<<(unsigned)((n1 / 4 + 255) / 256), 256>>>(gate_W,  wg, n1);
        f2h_kernel<<<(unsigned)((n1 / 4 + 255) / 256), 256>>>(value_W, wv, n1);
        f2h_kernel<<<(unsigned)((n2 / 4 + 255) / 256), 256>>>(ffn_W1,  w1, n2);
        f2h_kernel<<<(unsigned)((n2 / 4 + 255) / 256), 256>>>(ffn_W2,  w2, n2);
    }

    // 1. h = LN1(x) (half)
    ln_kernel<false><<<M_ROWS, 256>>>(x, nullptr, n1w, n1b, nullptr, h);

    // 2+3+4 fused: mem = chunked_scan(sigmoid(h@Wg+bg), h@Wv+bv)
    gemm_gv_scan<<<dim3(DIM / GBN, M_ROWS / GBM), 256, GSMEM_BYTES>>>(
        h, wg, wv, gate_b, value_b, mem);

    // 5. out = x + mem ; h = LN2(out) (half)
    ln_kernel<true><<<M_ROWS, 256>>>(x, mem, n2w, n2b, out, h);

    // 6. ffn = gelu(h @ W1 + b1)            (half out)
    gemm_fp16<ACT_GELU, false, true><<<dim3(DFF / BN, M_ROWS / BM), NTHREADS, SMEM_BYTES>>>(
        h, w1, ffn_b1, nullptr, ffn, DFF, DIM);
    // 7. out += ffn @ W2 + b2               (f32 out, residual)
    gemm_fp16<ACT_NONE, true, false><<<dim3(DIM / BN, M_ROWS / BM), NTHREADS, SMEM_BYTES>>>(
        ffn, w2, ffn_b2, out, nullptr, DIM, DFF);
}

// round 8
// speedup vs baseline: 9.1958x; 1.0236x over previous
#include <cuda_runtime.h>
#include <cuda_fp16.h>
#include <mma.h>
#include <math.h>
#include <stdint.h>

using namespace nvcuda;

// Problem constants
#define BATCH   4
#define SEQ     8192
#define DIM     768
#define CHUNK   64
#define M_ROWS  (BATCH * SEQ)       // 32768
#define DFF     (4 * DIM)           // 3072

// ---------------- scratch (static device globals) ----------------------------
__device__ __half g_h   [(size_t)M_ROWS * DIM];   // LN output (half)
__device__ float  g_mem [(size_t)M_ROWS * DIM];   // scan output (f32)
__device__ __half g_ffn [(size_t)M_ROWS * DFF];   // ffn hidden (half)
__device__ __half g_wg  [(size_t)DIM * DIM];      // gate_W  half [K,N]
__device__ __half g_wv  [(size_t)DIM * DIM];      // value_W half
__device__ __half g_w1  [(size_t)DIM * DFF];      // ffn_W1  half
__device__ __half g_w2  [(size_t)DFF * DIM];      // ffn_W2  half

// ---------------- cp.async helpers -------------------------------------------
__device__ __forceinline__ uint32_t smem_u32(const void* p) {
    uint32_t a;
    asm("{ .reg .u64 t; cvta.to.shared.u64 t, %1; cvt.u32.u64 %0, t; }"
        : "=r"(a) : "l"(p));
    return a;
}
#define CP_ASYNC16(dst, src) \
    asm volatile("cp.async.cg.shared.global [%0], [%1], 16;" :: "r"(dst), "l"(src))
#define CP_COMMIT() asm volatile("cp.async.commit_group;" ::: "memory")
#define CP_WAIT(n)  asm volatile("cp.async.wait_group %0;" :: "n"(n) : "memory")

// ---------------- block-wide sum over 256 threads ----------------------------
__device__ __forceinline__ float block_sum_256(float v) {
    __shared__ float sh[8];
    int lane = threadIdx.x & 31;
    int wrp  = threadIdx.x >> 5;
    #pragma unroll
    for (int o = 16; o > 0; o >>= 1) v += __shfl_xor_sync(0xffffffffu, v, o);
    if (lane == 0) sh[wrp] = v;
    __syncthreads();
    if (wrp == 0) {
        float t = (lane < 8) ? sh[lane] : 0.0f;
        #pragma unroll
        for (int o = 4; o > 0; o >>= 1) t += __shfl_xor_sync(0xffffffffu, t, o);
        if (lane == 0) sh[0] = t;
    }
    __syncthreads();
    float r = sh[0];
    __syncthreads();
    return r;
}

// ---------------- LayerNorm: h (half) out, optional residual add -------------
template <bool ADD_MEM>
__global__ void ln_kernel(const float* __restrict__ x,
                          const float* __restrict__ mem,
                          const float* __restrict__ w,
                          const float* __restrict__ b,
                          float* __restrict__ xout,
                          __half* __restrict__ hout) {
    const size_t base = (size_t)blockIdx.x * DIM;
    const int tid = threadIdx.x;
    float vals[3];
    #pragma unroll
    for (int i = 0; i < 3; i++) {
        int c = tid + i * 256;
        float xv = x[base + c];
        if (ADD_MEM) { xv += mem[base + c]; xout[base + c] = xv; }
        vals[i] = xv;
    }
    float mu = block_sum_256(vals[0] + vals[1] + vals[2]) * (1.0f / DIM);
    float sq = 0.0f;
    #pragma unroll
    for (int i = 0; i < 3; i++) { float d = vals[i] - mu; sq += d * d; }
    float inv = rsqrtf(block_sum_256(sq) * (1.0f / DIM) + 1e-5f);
    #pragma unroll
    for (int i = 0; i < 3; i++) {
        int c = tid + i * 256;
        hout[base + c] = __float2half_rn((vals[i] - mu) * inv * w[c] + b[c]);
    }
}

// ---------------- f32 -> f16 convert (weights) --------------------------------
__global__ void f2h_kernel(const float* __restrict__ src, __half* __restrict__ dst,
                           size_t n) {
    size_t i = ((size_t)blockIdx.x * 256 + threadIdx.x) * 4;
    if (i + 3 < n) {
        float4 v = *reinterpret_cast<const float4*>(src + i);
        __half2 h0 = __floats2half2_rn(v.x, v.y);
        __half2 h1 = __floats2half2_rn(v.z, v.w);
        *reinterpret_cast<__half2*>(dst + i)     = h0;
        *reinterpret_cast<__half2*>(dst + i + 2) = h1;
    }
}

// =============== Fused gate+value GEMM + chunked scan (512 threads) ===========
#define GBM 256
#define GBN 64
#define GKT 64
#define GLDA 72
#define GLDB 72
#define GA_ST (GBM * GLDA)              // 18432 halfs
#define GB_ST (GKT * GLDB)              // 4608 halfs (per weight matrix)
#define GST_HALFS (GA_ST + 2 * GB_ST)   // 27648 halfs = 55296 B
#define GSMEM_BYTES (3 * GST_HALFS * 2) // 165888 B
#define GNT 512

__global__ __launch_bounds__(GNT, 1)
void gemm_gv_scan(const __half* __restrict__ A, const __half* __restrict__ Wg,
                  const __half* __restrict__ Wv,
                  const float* __restrict__ gate_b,
                  const float* __restrict__ value_b,
                  float* __restrict__ mem_out) {
    extern __shared__ __align__(16) __half smem[];
    const int tid  = threadIdx.x;
    const int wid  = tid >> 5;      // 0..15
    const int lane = tid & 31;
    const int wm   = wid >> 2;      // 0..3 -> 64-row chunk (== CHUNK)
    const int wn   = wid & 3;       // 0..3 -> 16-col band

    const int bm = blockIdx.y * GBM;
    const int bn = blockIdx.x * GBN;
    const int K = DIM, N = DIM;
    const int kiters = K / GKT;     // 12

    const uint32_t smem_base = smem_u32(smem);

    auto load_stage = [&](int buf, int ki) {
        const int k0 = ki * GKT;
        const uint32_t stA  = smem_base + (uint32_t)buf * GST_HALFS * 2;
        const uint32_t stBg = stA + GA_ST * 2;
        const uint32_t stBv = stBg + GB_ST * 2;
        // A: 256 x 64 halfs = 2048 16B-chunks; 4 per thread
        #pragma unroll
        for (int u = 0; u < 4; u++) {
            int f = tid + u * GNT;
            int row = f >> 3, cc = f & 7;
            CP_ASYNC16(stA + (uint32_t)(row * GLDA + cc * 8) * 2,
                       A + (size_t)(bm + row) * K + k0 + cc * 8);
        }
        // Bg, Bv: 64 x 64 halfs = 512 chunks each; 1 per thread each
        {
            int row = tid >> 3, cc = tid & 7;
            CP_ASYNC16(stBg + (uint32_t)(row * GLDB + cc * 8) * 2,
                       Wg + (size_t)(k0 + row) * N + bn + cc * 8);
            CP_ASYNC16(stBv + (uint32_t)(row * GLDB + cc * 8) * 2,
                       Wv + (size_t)(k0 + row) * N + bn + cc * 8);
        }
    };

    wmma::fragment<wmma::accumulator, 16, 16, 16, float> accg[4], accv[4];
    #pragma unroll
    for (int i = 0; i < 4; i++) {
        wmma::fill_fragment(accg[i], 0.0f);
        wmma::fill_fragment(accv[i], 0.0f);
    }

    #pragma unroll
    for (int s = 0; s < 2; s++) { load_stage(s, s); CP_COMMIT(); }

    for (int ki = 0; ki < kiters; ki++) {
        CP_WAIT(1);
        __syncthreads();

        int nxt = ki + 2;
        if (nxt < kiters) load_stage(nxt % 3, nxt);
        CP_COMMIT();

        const int buf = ki % 3;
        const __half* sA  = smem + (size_t)buf * GST_HALFS;
        const __half* sBg = sA + GA_ST;
        const __half* sBv = sBg + GB_ST;

        #pragma unroll
        for (int kk = 0; kk < GKT; kk += 16) {
            wmma::fragment<wmma::matrix_a, 16, 16, 16, __half, wmma::row_major> af[4];
            wmma::fragment<wmma::matrix_b, 16, 16, 16, __half, wmma::row_major> bgf, bvf;
            #pragma unroll
            for (int i = 0; i < 4; i++)
                wmma::load_matrix_sync(af[i], sA + (wm * 64 + i * 16) * GLDA + kk, GLDA);
            wmma::load_matrix_sync(bgf, sBg + kk * GLDB + wn * 16, GLDB);
            wmma::load_matrix_sync(bvf, sBv + kk * GLDB + wn * 16, GLDB);
            #pragma unroll
            for (int i = 0; i < 4; i++) {
                wmma::mma_sync(accg[i], af[i], bgf, accg[i]);
                wmma::mma_sync(accv[i], af[i], bvf, accv[i]);
            }
        }
    }

    // ---------------- epilogue: stage + per-column chunked scan ---------------
    __syncthreads();
    // per-warp staging: 64 rows x 20 floats x 2 matrices = 10240 B; x16 = 160KB
    float* gt = reinterpret_cast<float*>(smem) + (size_t)wid * (2 * 64 * 20);
    float* vt = gt + 64 * 20;
    #pragma unroll
    for (int i = 0; i < 4; i++) {
        wmma::store_matrix_sync(gt + i * 16 * 20, accg[i], 20, wmma::mem_row_major);
        wmma::store_matrix_sync(vt + i * 16 * 20, accv[i], 20, wmma::mem_row_major);
    }
    __syncwarp();

    // Lanes 0..15 each own one feature column; warp rows == one CHUNK == 64.
    if (lane < 16) {
        const int gcol = bn + wn * 16 + lane;
        const float bg = gate_b[gcol];
        const float bv = value_b[gcol];
        float sg = 0.0f, sgv = 0.0f;
        const size_t rbase = (size_t)(bm + wm * 64) * DIM + gcol;
        #pragma unroll 4
        for (int r = 0; r < 64; r++) {
            float gval = gt[r * 20 + lane] + bg;
            gval = 1.0f / (1.0f + expf(-gval));
            float vval = vt[r * 20 + lane] + bv;
            sg  += gval;
            sgv += gval * vval;
            mem_out[rbase + (size_t)r * DIM] = sgv / (sg + 1e-6f);
        }
    }
}

// ---------------- FFN GEMM: 512 threads, 16 warps, 4-stage, warp 64x32 --------
#define BM 256
#define BN 128
#define KT 64
#define NSTAGE 4
#define LDA 72
#define LDB 136
#define A_ST (BM * LDA)
#define B_ST (KT * LDB)
#define ST_HALFS (A_ST + B_ST)
#define SMEM_BYTES (NSTAGE * ST_HALFS * 2)   // 217088 B
#define NTHREADS 512

#define ACT_NONE 0
#define ACT_GELU 2

template <int ACT, bool ADD_OUT, bool OUT_HALF>
__global__ __launch_bounds__(NTHREADS, 1)
void gemm_fp16(const __half* __restrict__ A, const __half* __restrict__ B,
               const float* __restrict__ bias, float* __restrict__ Cf,
               __half* __restrict__ Ch, int N, int K) {
    extern __shared__ __align__(16) __half smem[];
    const int tid  = threadIdx.x;
    const int wid  = tid >> 5;      // 0..15
    const int lane = tid & 31;
    const int wm   = wid >> 2;      // 0..3 -> 64-row band
    const int wn   = wid & 3;       // 0..3 -> 32-col band

    const int bm = blockIdx.y * BM;
    const int bn = blockIdx.x * BN;
    const int kiters = K / KT;

    const uint32_t smem_base = smem_u32(smem);

    auto load_stage = [&](int buf, int ki) {
        const int k0 = ki * KT;
        const uint32_t stA = smem_base + (uint32_t)buf * ST_HALFS * 2;
        const uint32_t stB = stA + A_ST * 2;
        #pragma unroll
        for (int u = 0; u < 4; u++) {
            int f = tid + u * NTHREADS;
            int row = f >> 3, cc = f & 7;
            CP_ASYNC16(stA + (uint32_t)(row * LDA + cc * 8) * 2,
                       A + (size_t)(bm + row) * K + k0 + cc * 8);
        }
        #pragma unroll
        for (int u = 0; u < 2; u++) {
            int f = tid + u * NTHREADS;
            int row = f >> 4, cc = f & 15;
            CP_ASYNC16(stB + (uint32_t)(row * LDB + cc * 8) * 2,
                       B + (size_t)(k0 + row) * N + bn + cc * 8);
        }
    };

    wmma::fragment<wmma::accumulator, 16, 16, 16, float> acc[4][2];
    #pragma unroll
    for (int i = 0; i < 4; i++)
        #pragma unroll
        for (int j = 0; j < 2; j++)
            wmma::fill_fragment(acc[i][j], 0.0f);

    #pragma unroll
    for (int s = 0; s < NSTAGE - 1; s++) { load_stage(s, s); CP_COMMIT(); }

    for (int ki = 0; ki < kiters; ki++) {
        CP_WAIT(NSTAGE - 2);
        __syncthreads();

        int nxt = ki + NSTAGE - 1;
        if (nxt < kiters) load_stage(nxt % NSTAGE, nxt);
        CP_COMMIT();

        const int buf = ki % NSTAGE;
        const __half* sA = smem + (size_t)buf * ST_HALFS;
        const __half* sB = sA + A_ST;

        #pragma unroll
        for (int kk = 0; kk < KT; kk += 16) {
            wmma::fragment<wmma::matrix_a, 16, 16, 16, __half, wmma::row_major> af[4];
            wmma::fragment<wmma::matrix_b, 16, 16, 16, __half, wmma::row_major> bf[2];
            #pragma unroll
            for (int i = 0; i < 4; i++)
                wmma::load_matrix_sync(af[i], sA + (wm * 64 + i * 16) * LDA + kk, LDA);
            #pragma unroll
            for (int j = 0; j < 2; j++)
                wmma::load_matrix_sync(bf[j], sB + kk * LDB + wn * 32 + j * 16, LDB);
            #pragma unroll
            for (int i = 0; i < 4; i++)
                #pragma unroll
                for (int j = 0; j < 2; j++)
                    wmma::mma_sync(acc[i][j], af[i], bf[j], acc[i][j]);
        }
    }

    // ---------------- epilogue: per-warp smem staging, fused bias/act ---------
    __syncthreads();
    float* stile = reinterpret_cast<float*>(smem) + (size_t)wid * 32 * 36;

    #pragma unroll
    for (int h = 0; h < 2; h++) {          // two 32-row halves of the 64x32 warp tile
        #pragma unroll
        for (int j = 0; j < 2; j++)
            wmma::store_matrix_sync(stile + j * 16,
                                    acc[h * 2 + 0][j], 36, wmma::mem_row_major);
        #pragma unroll
        for (int j = 0; j < 2; j++)
            wmma::store_matrix_sync(stile + 16 * 36 + j * 16,
                                    acc[h * 2 + 1][j], 36, wmma::mem_row_major);
        __syncwarp();
        if (OUT_HALF) {
            // 32x32 tile as 32x16 half2 stores; 16 iters of 32 lanes
            #pragma unroll
            for (int it = 0; it < 16; it++) {
                int idx = it * 32 + lane;
                int row = idx >> 4;
                int cp  = idx & 15;          // column pair
                int grow = bm + wm * 64 + h * 32 + row;
                int gcol = bn + wn * 32 + cp * 2;
                float v0 = stile[row * 36 + cp * 2 + 0] + bias[gcol + 0];
                float v1 = stile[row * 36 + cp * 2 + 1] + bias[gcol + 1];
                if (ACT == ACT_GELU) {
                    v0 = 0.5f * v0 * (1.0f + erff(v0 * 0.70710678118654752f));
                    v1 = 0.5f * v1 * (1.0f + erff(v1 * 0.70710678118654752f));
                }
                *reinterpret_cast<__half2*>(Ch + (size_t)grow * N + gcol) =
                    __floats2half2_rn(v0, v1);
            }
        } else {
            #pragma unroll
            for (int it = 0; it < 32; it++) {
                int idx = it * 32 + lane;
                int row = idx >> 5;
                int col = idx & 31;
                int grow = bm + wm * 64 + h * 32 + row;
                int gcol = bn + wn * 32 + col;
                float val = stile[row * 36 + col] + bias[gcol];
                if (ACT == ACT_GELU) val = 0.5f * val * (1.0f + erff(val * 0.70710678118654752f));
                const size_t gidx = (size_t)grow * N + gcol;
                if (ADD_OUT) val += Cf[gidx];
                Cf[gidx] = val;
            }
        }
        __syncwarp();
    }
}

// ---------------- launcher ----------------------------------------------------
extern "C" void kernel_launch(void* const* d_in, const int* in_sizes, int n_in,
                              void* d_out, int out_size) {
    const float* x       = (const float*)d_in[0];
    const float* n1w     = (const float*)d_in[1];
    const float* n1b     = (const float*)d_in[2];
    const float* n2w     = (const float*)d_in[3];
    const float* n2b     = (const float*)d_in[4];
    const float* gate_W  = (const float*)d_in[5];
    const float* gate_b  = (const float*)d_in[6];
    const float* value_W = (const float*)d_in[7];
    const float* value_b = (const float*)d_in[8];
    const float* ffn_W1  = (const float*)d_in[9];
    const float* ffn_b1  = (const float*)d_in[10];
    const float* ffn_W2  = (const float*)d_in[11];
    const float* ffn_b2  = (const float*)d_in[12];
    float* out = (float*)d_out;

    __half *h, *ffn, *wg, *wv, *w1, *w2;
    float *mem;
    cudaGetSymbolAddress((void**)&h,   g_h);
    cudaGetSymbolAddress((void**)&mem, g_mem);
    cudaGetSymbolAddress((void**)&ffn, g_ffn);
    cudaGetSymbolAddress((void**)&wg,  g_wg);
    cudaGetSymbolAddress((void**)&wv,  g_wv);
    cudaGetSymbolAddress((void**)&w1,  g_w1);
    cudaGetSymbolAddress((void**)&w2,  g_w2);

    cudaFuncSetAttribute(gemm_gv_scan,
                         cudaFuncAttributeMaxDynamicSharedMemorySize, GSMEM_BYTES);
    cudaFuncSetAttribute(gemm_fp16<ACT_GELU, false, true>,
                         cudaFuncAttributeMaxDynamicSharedMemorySize, SMEM_BYTES);
    cudaFuncSetAttribute(gemm_fp16<ACT_NONE, true,  false>,
                         cudaFuncAttributeMaxDynamicSharedMemorySize, SMEM_BYTES);

    // 0. convert weights to half
    {
        size_t n1 = (size_t)DIM * DIM;
        size_t n2 = (size_t)DIM * DFF;
        f2h_kernel<<<(unsigned)((n1 / 4 + 255) / 256), 256>>>(gate_W,  wg, n1);
        f2h_kernel<<<(unsigned)((n1 / 4 + 255) / 256), 256>>>(value_W, wv, n1);
        f2h_kernel<<<(unsigned)((n2 / 4 + 255) / 256), 256>>>(ffn_W1,  w1, n2);
        f2h_kernel<<<(unsigned)((n2 / 4 + 255) / 256), 256>>>(ffn_W2,  w2, n2);
    }

    // 1. h = LN1(x) (half)
    ln_kernel<false><<<M_ROWS, 256>>>(x, nullptr, n1w, n1b, nullptr, h);

    // 2+3+4 fused: mem = chunked_scan(sigmoid(h@Wg+bg), h@Wv+bv)
    gemm_gv_scan<<<dim3(DIM / GBN, M_ROWS / GBM), GNT, GSMEM_BYTES>>>(
        h, wg, wv, gate_b, value_b, mem);

    // 5. out = x + mem ; h = LN2(out) (half)
    ln_kernel<true><<<M_ROWS, 256>>>(x, mem, n2w, n2b, out, h);

    // 6. ffn = gelu(h @ W1 + b1)            (half out)
    gemm_fp16<ACT_GELU, false, true><<<dim3(DFF / BN, M_ROWS / BM), NTHREADS, SMEM_BYTES>>>(
        h, w1, ffn_b1, nullptr, ffn, DFF, DIM);
    // 7. out += ffn @ W2 + b2               (f32 out, residual)
    gemm_fp16<ACT_NONE, true, false><<<dim3(DIM / BN, M_ROWS / BM), NTHREADS, SMEM_BYTES>>>(
        ffn, w2, ffn_b2, out, nullptr, DIM, DFF);
}